// round 2
// baseline (speedup 1.0000x reference)
#include <cuda_runtime.h>
#include <cstdint>

// ---------------------------------------------------------------------------
// Model_78898549227585: embed -> GRU encoder (T=5) -> GATConv -> GRUCell
// decoder (T_OUT=6, autoregressive) + confidence head.
// B=32768, N=5, H=64, F=10, M=5.
// ---------------------------------------------------------------------------

#define DINL __device__ __forceinline__

constexpr int Bq   = 32768;
constexpr int Tq   = 5;
constexpr int Nq   = 5;
constexpr int Fq   = 10;
constexpr int Hq   = 64;
constexpr int Gq   = 192;   // 3H
constexpr int Mq   = 5;
constexpr int TOq  = 6;
constexpr int BNq  = Bq * Nq;                       // 163840
constexpr long long TRAJ_ELEMS = (long long)Bq * Mq * Nq * TOq * 2;  // 9,830,400

// ------------------------- device scratch ---------------------------------
__device__ float g_Wc_enc[Gq * Fq];
__device__ float g_bc_enc[Gq];
__device__ float g_Wc_dec[Gq * 2];
__device__ float g_bc_dec[Gq];
__device__ float g_Wc_xl[Fq * Hq];
__device__ float g_b_xl[Hq];

__device__ float g_henc[(size_t)BNq * Hq];
__device__ float g_xl  [(size_t)BNq * Hq];
__device__ float g_as  [BNq];
__device__ float g_ad  [BNq];
__device__ int   g_mask[BNq];
__device__ float g_hfin[(size_t)BNq * Hq];

// ------------------------- math helpers -----------------------------------
DINL float sigmf(float v)  { return __fdividef(1.f, 1.f + __expf(-v)); }
DINL float tanhf_(float v) { return 1.f - __fdividef(2.f, __expf(2.f * v) + 1.f); }

// ------------------------- prep: fold weights ------------------------------
// Wc_enc[j,c]  = sum_k enc_Wih[j,k] * embed_W[c,k]
// bc_enc[j]    = enc_bih[j] + sum_k enc_Wih[j,k] * embed_b[k]
// Wc_dec[j,c]  = sum_k dec_Wih[j,k] * proj_W[c,k]
// bc_dec[j]    = dec_bih[j] + sum_k dec_Wih[j,k] * proj_b[k]
// Wc_xl[c,k2]  = sum_k embed_W[c,k] * gat_W[k,k2]
// b_xl[k2]     = sum_k embed_b[k]   * gat_W[k,k2]
__global__ void prep_kernel(const float* __restrict__ enc_Wih,
                            const float* __restrict__ enc_bih,
                            const float* __restrict__ dec_Wih,
                            const float* __restrict__ dec_bih,
                            const float* __restrict__ embW,
                            const float* __restrict__ embB,
                            const float* __restrict__ projW,
                            const float* __restrict__ projB,
                            const float* __restrict__ gatW)
{
    int t = blockIdx.x * blockDim.x + threadIdx.x;
    if (t < Gq * Fq) {                                   // 0..1919
        int j = t / Fq, c = t % Fq;
        float s = 0.f;
        for (int k = 0; k < Hq; k++) s += enc_Wih[j * Hq + k] * embW[c * Hq + k];
        g_Wc_enc[j * Fq + c] = s;
    } else if (t < 1920 + 192) {                         // bc_enc
        int j = t - 1920;
        float s = enc_bih[j];
        for (int k = 0; k < Hq; k++) s += enc_Wih[j * Hq + k] * embB[k];
        g_bc_enc[j] = s;
    } else if (t < 2112 + 384) {                         // Wc_dec
        int i = t - 2112;
        int j = i / 2, c = i % 2;
        float s = 0.f;
        for (int k = 0; k < Hq; k++) s += dec_Wih[j * Hq + k] * projW[c * Hq + k];
        g_Wc_dec[j * 2 + c] = s;
    } else if (t < 2496 + 192) {                         // bc_dec
        int j = t - 2496;
        float s = dec_bih[j];
        for (int k = 0; k < Hq; k++) s += dec_Wih[j * Hq + k] * projB[k];
        g_bc_dec[j] = s;
    } else if (t < 2688 + 640) {                         // Wc_xl
        int i = t - 2688;
        int c = i / Hq, k2 = i % Hq;
        float s = 0.f;
        for (int k = 0; k < Hq; k++) s += embW[c * Hq + k] * gatW[k * Hq + k2];
        g_Wc_xl[c * Hq + k2] = s;
    } else if (t < 3328 + 64) {                          // b_xl
        int k2 = t - 3328;
        float s = 0.f;
        for (int k = 0; k < Hq; k++) s += embB[k] * gatW[k * Hq + k2];
        g_b_xl[k2] = s;
    }
}

// ------------------------- encoder ------------------------------------------
// smem layout (floats):
//  sWhh 12288 | sBhh 192 | sWc 1920 | sBc 192 | sWxl 640 | sBxl 64 |
//  sAs 64 | sAd 64 | hs 64*128
constexpr int ENC_SMEM_FLOATS = 12288 + 192 + 1920 + 192 + 640 + 64 + 64 + 64 + 64 * 128;
constexpr int ENC_SMEM_BYTES  = ENC_SMEM_FLOATS * 4;   // 94464

__global__ void __launch_bounds__(128) enc_kernel(
    const float* __restrict__ x,
    const float* __restrict__ Whh,
    const float* __restrict__ bhh,
    const float* __restrict__ asrc,
    const float* __restrict__ adst)
{
    extern __shared__ float sm[];
    float* sWhh = sm;
    float* sBhh = sm + 12288;
    float* sWc  = sm + 12480;
    float* sBc  = sm + 14400;
    float* sWxl = sm + 14592;
    float* sBxl = sm + 15232;
    float* sAs  = sm + 15296;
    float* sAd  = sm + 15360;
    float* hs   = sm + 15424;

    const int tid = threadIdx.x;
    for (int i = tid; i < 12288; i += 128) sWhh[i] = Whh[i];
    for (int i = tid; i < 192;   i += 128) sBhh[i] = bhh[i];
    for (int i = tid; i < 1920;  i += 128) sWc[i]  = g_Wc_enc[i];
    for (int i = tid; i < 192;   i += 128) sBc[i]  = g_bc_enc[i];
    for (int i = tid; i < 640;   i += 128) sWxl[i] = g_Wc_xl[i];
    if (tid < 64) { sBxl[tid] = g_b_xl[tid]; sAs[tid] = asrc[tid]; sAd[tid] = adst[tid]; }
    #pragma unroll
    for (int k = 0; k < 64; k++) hs[k * 128 + tid] = 0.f;
    __syncthreads();

    const int bn = blockIdx.x * 128 + tid;
    const int b  = bn / Nq;
    const int n  = bn % Nq;
    const float* xp = x + ((size_t)b * (Tq * Nq) + n) * Fq;

    float h[64];
    #pragma unroll
    for (int k = 0; k < 64; k++) h[k] = 0.f;

    float x10[10];
    const float4* W4 = reinterpret_cast<const float4*>(sWhh);

    for (int t = 0; t < Tq; t++) {
        #pragma unroll
        for (int f = 0; f < 10; f++) x10[f] = xp[(size_t)t * (Nq * Fq) + f];

        #pragma unroll 1
        for (int j = 0; j < 64; j++) {
            float ar = sBhh[j], az = sBhh[j + 64], an = sBhh[j + 128];
            #pragma unroll
            for (int k4 = 0; k4 < 16; k4++) {
                float4 wr = W4[j * 16 + k4];
                float4 wz = W4[(j + 64) * 16 + k4];
                float4 wn = W4[(j + 128) * 16 + k4];
                float h0 = h[4 * k4], h1 = h[4 * k4 + 1], h2 = h[4 * k4 + 2], h3 = h[4 * k4 + 3];
                ar += wr.x * h0 + wr.y * h1 + wr.z * h2 + wr.w * h3;
                az += wz.x * h0 + wz.y * h1 + wz.z * h2 + wz.w * h3;
                an += wn.x * h0 + wn.y * h1 + wn.z * h2 + wn.w * h3;
            }
            float xr = sBc[j], xz = sBc[j + 64], xn = sBc[j + 128];
            #pragma unroll
            for (int c = 0; c < 10; c++) {
                xr += sWc[j * 10 + c]         * x10[c];
                xz += sWc[(j + 64) * 10 + c]  * x10[c];
                xn += sWc[(j + 128) * 10 + c] * x10[c];
            }
            float r  = sigmf(xr + ar);
            float z  = sigmf(xz + az);
            float nn = tanhf_(xn + r * an);
            float hold = hs[j * 128 + tid];
            hs[j * 128 + tid] = (1.f - z) * nn + z * hold;
        }
        #pragma unroll
        for (int k = 0; k < 64; k++) h[k] = hs[k * 128 + tid];
    }

    // store h_enc
    float4* he4 = reinterpret_cast<float4*>(g_henc + (size_t)bn * 64);
    #pragma unroll
    for (int k4 = 0; k4 < 16; k4++)
        he4[k4] = make_float4(h[4 * k4], h[4 * k4 + 1], h[4 * k4 + 2], h[4 * k4 + 3]);

    // mask from last frame (x10 holds t=4)
    float s6 = x10[0] + x10[1] + x10[2] + x10[3] + x10[4] + x10[5];
    g_mask[bn] = (s6 != 0.f) ? 1 : 0;

    // GAT transformed features + attention scalars
    float as_ = 0.f, ad_ = 0.f;
    for (int k = 0; k < 64; k++) {
        float acc = sBxl[k];
        #pragma unroll
        for (int c = 0; c < 10; c++) acc += x10[c] * sWxl[c * 64 + k];
        g_xl[(size_t)bn * 64 + k] = acc;
        as_ += acc * sAs[k];
        ad_ += acc * sAd[k];
    }
    g_as[bn] = as_;
    g_ad[bn] = ad_;
}

// ------------------------- GAT + conf ---------------------------------------
__global__ void __launch_bounds__(128) gat_kernel(
    const float* __restrict__ gat_b,
    const float* __restrict__ cW1,
    const float* __restrict__ cB1,
    const float* __restrict__ cW2,
    const float* __restrict__ cB2,
    float* __restrict__ out)
{
    __shared__ float sW1t[4096];   // [m][k]
    __shared__ float sB1[64];
    __shared__ float sW2[320];     // [m][p]
    __shared__ float sB2[5];
    __shared__ float sGb[64];

    const int tid = threadIdx.x;
    for (int i = tid; i < 4096; i += 128) {
        int m = i >> 6, k = i & 63;
        sW1t[i] = cW1[k * 64 + m];
    }
    for (int i = tid; i < 320; i += 128) sW2[i] = cW2[i];
    if (tid < 64) { sB1[tid] = cB1[tid]; sGb[tid] = gat_b[tid]; }
    if (tid < 5)  sB2[tid] = cB2[tid];
    __syncthreads();

    const int bn = blockIdx.x * 128 + tid;
    const int b  = bn / Nq;
    const int n  = bn % Nq;
    const int base = b * Nq;

    float ad_i = g_ad[bn];
    int   mi   = g_mask[bn];

    float w[5];
    float amax = -1e30f;
    #pragma unroll
    for (int j = 0; j < 5; j++) {
        int src = base + j;
        float a = g_as[src] + ad_i;
        a = a > 0.f ? a : 0.2f * a;
        bool valid = (j == n) ? true : (mi && g_mask[src]);
        w[j] = valid ? a : -1e30f;
        amax = fmaxf(amax, w[j]);
    }
    float denom = 0.f;
    #pragma unroll
    for (int j = 0; j < 5; j++) {
        float e = __expf(w[j] - amax);   // invalid: exp(-huge) -> 0
        w[j] = e;
        denom += e;
    }
    float inv = __fdividef(1.f, denom);
    #pragma unroll
    for (int j = 0; j < 5; j++) w[j] *= inv;

    float4 acc[16];
    #pragma unroll
    for (int k4 = 0; k4 < 16; k4++) acc[k4] = make_float4(0.f, 0.f, 0.f, 0.f);
    #pragma unroll
    for (int j = 0; j < 5; j++) {
        const float4* xr = reinterpret_cast<const float4*>(g_xl + (size_t)(base + j) * 64);
        float wj = w[j];
        #pragma unroll
        for (int k4 = 0; k4 < 16; k4++) {
            float4 v = xr[k4];
            acc[k4].x += wj * v.x; acc[k4].y += wj * v.y;
            acc[k4].z += wj * v.z; acc[k4].w += wj * v.w;
        }
    }

    float hf[64];
    const float4* he4 = reinterpret_cast<const float4*>(g_henc + (size_t)bn * 64);
    const float4* gb4 = reinterpret_cast<const float4*>(sGb);
    float4* hfo = reinterpret_cast<float4*>(g_hfin + (size_t)bn * 64);
    #pragma unroll
    for (int k4 = 0; k4 < 16; k4++) {
        float4 hv = he4[k4];
        float4 g  = gb4[k4];
        float4 r;
        r.x = hv.x + acc[k4].x + g.x;
        r.y = hv.y + acc[k4].y + g.y;
        r.z = hv.z + acc[k4].z + g.z;
        r.w = hv.w + acc[k4].w + g.w;
        hfo[k4] = r;
        hf[4 * k4] = r.x; hf[4 * k4 + 1] = r.y; hf[4 * k4 + 2] = r.z; hf[4 * k4 + 3] = r.w;
    }

    // conf head
    float o[5];
    #pragma unroll
    for (int p = 0; p < 5; p++) o[p] = sB2[p];
    #pragma unroll 1
    for (int m = 0; m < 64; m++) {
        float t = sB1[m];
        const float4* w1 = reinterpret_cast<const float4*>(sW1t + m * 64);
        #pragma unroll
        for (int k4 = 0; k4 < 16; k4++) {
            float4 wv = w1[k4];
            t += wv.x * hf[4 * k4] + wv.y * hf[4 * k4 + 1]
               + wv.z * hf[4 * k4 + 2] + wv.w * hf[4 * k4 + 3];
        }
        t = fmaxf(t, 0.f);
        #pragma unroll
        for (int p = 0; p < 5; p++) o[p] += t * sW2[m * 5 + p];
    }
    float mx = o[0];
    #pragma unroll
    for (int p = 1; p < 5; p++) mx = fmaxf(mx, o[p]);
    float s = 0.f;
    #pragma unroll
    for (int p = 0; p < 5; p++) { o[p] = __expf(o[p] - mx); s += o[p]; }
    float invs = __fdividef(1.f, s);

    float* conf = out + TRAJ_ELEMS;
    #pragma unroll
    for (int p = 0; p < 5; p++)
        conf[(size_t)b * 25 + p * 5 + n] = o[p] * invs;
}

// ------------------------- decoder ------------------------------------------
// smem layout (floats):
//  sWhh 12288 | sBhh 192 | sWcd 384 | sBcd 192 | sW1t 4096 | sB1 64 |
//  sW2 640 | sB2 16 | hs 8192
constexpr int DEC_SMEM_FLOATS = 12288 + 192 + 384 + 192 + 4096 + 64 + 640 + 16 + 64 * 128;
constexpr int DEC_SMEM_BYTES  = DEC_SMEM_FLOATS * 4;   // 104256

__global__ void __launch_bounds__(128) dec_kernel(
    const float* __restrict__ x,
    const float* __restrict__ Whh,
    const float* __restrict__ bhh,
    const float* __restrict__ oW1,
    const float* __restrict__ oB1,
    const float* __restrict__ oW2,
    const float* __restrict__ oB2,
    float* __restrict__ out)
{
    extern __shared__ float sm[];
    float* sWhh = sm;
    float* sBhh = sm + 12288;
    float* sWcd = sm + 12480;
    float* sBcd = sm + 12864;
    float* sW1t = sm + 13056;
    float* sB1  = sm + 17152;
    float* sW2  = sm + 17216;
    float* sB2  = sm + 17856;
    float* hs   = sm + 17872;

    const int tid = threadIdx.x;
    for (int i = tid; i < 12288; i += 128) sWhh[i] = Whh[i];
    for (int i = tid; i < 192;   i += 128) sBhh[i] = bhh[i];
    for (int i = tid; i < 384;   i += 128) sWcd[i] = g_Wc_dec[i];
    for (int i = tid; i < 192;   i += 128) sBcd[i] = g_bc_dec[i];
    for (int i = tid; i < 4096;  i += 128) {
        int m = i >> 6, k = i & 63;
        sW1t[i] = oW1[k * 64 + m];
    }
    for (int i = tid; i < 640;   i += 128) sW2[i] = oW2[i];
    if (tid < 64) sB1[tid] = oB1[tid];
    if (tid < 10) sB2[tid] = oB2[tid];
    __syncthreads();

    const int bn = blockIdx.x * 128 + tid;
    const int b  = bn / Nq;
    const int n  = bn % Nq;

    float h[64];
    const float4* hf4 = reinterpret_cast<const float4*>(g_hfin + (size_t)bn * 64);
    #pragma unroll
    for (int k4 = 0; k4 < 16; k4++) {
        float4 v = hf4[k4];
        h[4 * k4] = v.x; h[4 * k4 + 1] = v.y; h[4 * k4 + 2] = v.z; h[4 * k4 + 3] = v.w;
    }
    #pragma unroll
    for (int k = 0; k < 64; k++) hs[k * 128 + tid] = h[k];

    // last-frame xy
    const float* xl = x + ((size_t)b * (Tq * Nq) + 4 * Nq + n) * Fq;
    float xy0 = xl[0];
    float xy1 = xl[1];

    const float4* W4 = reinterpret_cast<const float4*>(sWhh);
    const float4* W1t4 = reinterpret_cast<const float4*>(sW1t);

    for (int t = 0; t < TOq; t++) {
        #pragma unroll 1
        for (int j = 0; j < 64; j++) {
            float ar = sBhh[j], az = sBhh[j + 64], an = sBhh[j + 128];
            #pragma unroll
            for (int k4 = 0; k4 < 16; k4++) {
                float4 wr = W4[j * 16 + k4];
                float4 wz = W4[(j + 64) * 16 + k4];
                float4 wn = W4[(j + 128) * 16 + k4];
                float h0 = h[4 * k4], h1 = h[4 * k4 + 1], h2 = h[4 * k4 + 2], h3 = h[4 * k4 + 3];
                ar += wr.x * h0 + wr.y * h1 + wr.z * h2 + wr.w * h3;
                az += wz.x * h0 + wz.y * h1 + wz.z * h2 + wz.w * h3;
                an += wn.x * h0 + wn.y * h1 + wn.z * h2 + wn.w * h3;
            }
            float xr = sBcd[j]       + sWcd[j * 2] * xy0         + sWcd[j * 2 + 1] * xy1;
            float xz = sBcd[j + 64]  + sWcd[(j + 64) * 2] * xy0  + sWcd[(j + 64) * 2 + 1] * xy1;
            float xn = sBcd[j + 128] + sWcd[(j + 128) * 2] * xy0 + sWcd[(j + 128) * 2 + 1] * xy1;
            float r  = sigmf(xr + ar);
            float z  = sigmf(xz + az);
            float nn = tanhf_(xn + r * an);
            float hold = hs[j * 128 + tid];
            hs[j * 128 + tid] = (1.f - z) * nn + z * hold;
        }
        #pragma unroll
        for (int k = 0; k < 64; k++) h[k] = hs[k * 128 + tid];

        // out MLP: o2 = relu(h @ W1 + b1) @ W2 + b2, o1 never materialized
        float o2[10];
        #pragma unroll
        for (int p = 0; p < 10; p++) o2[p] = sB2[p];
        #pragma unroll 1
        for (int m = 0; m < 64; m++) {
            float a = sB1[m];
            #pragma unroll
            for (int k4 = 0; k4 < 16; k4++) {
                float4 wv = W1t4[m * 16 + k4];
                a += wv.x * h[4 * k4] + wv.y * h[4 * k4 + 1]
                   + wv.z * h[4 * k4 + 2] + wv.w * h[4 * k4 + 3];
            }
            a = fmaxf(a, 0.f);
            #pragma unroll
            for (int p = 0; p < 10; p++) o2[p] += a * sW2[m * 10 + p];
        }

        // traj[b, m, n, t, c] = o2[c*5 + m]
        size_t ob = (size_t)b * 300 + (size_t)n * 12 + t * 2;
        #pragma unroll
        for (int m = 0; m < 5; m++) {
            out[ob + m * 60 + 0] = o2[m];        // c = 0
            out[ob + m * 60 + 1] = o2[5 + m];    // c = 1
        }
        xy0 = o2[0];
        xy1 = o2[5];
    }
}

// ------------------------- launch -------------------------------------------
extern "C" void kernel_launch(void* const* d_in, const int* in_sizes, int n_in,
                              void* d_out, int out_size)
{
    const float* x        = (const float*)d_in[0];
    const float* embW     = (const float*)d_in[1];
    const float* embB     = (const float*)d_in[2];
    const float* gatW     = (const float*)d_in[3];
    const float* attSrc   = (const float*)d_in[4];
    const float* attDst   = (const float*)d_in[5];
    const float* gatB     = (const float*)d_in[6];
    const float* encWih   = (const float*)d_in[7];
    const float* encWhh   = (const float*)d_in[8];
    const float* encBih   = (const float*)d_in[9];
    const float* encBhh   = (const float*)d_in[10];
    const float* decWih   = (const float*)d_in[11];
    const float* decWhh   = (const float*)d_in[12];
    const float* decBih   = (const float*)d_in[13];
    const float* decBhh   = (const float*)d_in[14];
    const float* oW1      = (const float*)d_in[15];
    const float* oB1      = (const float*)d_in[16];
    const float* oW2      = (const float*)d_in[17];
    const float* oB2      = (const float*)d_in[18];
    const float* projW    = (const float*)d_in[19];
    const float* projB    = (const float*)d_in[20];
    const float* cW1      = (const float*)d_in[21];
    const float* cB1      = (const float*)d_in[22];
    const float* cW2      = (const float*)d_in[23];
    const float* cB2      = (const float*)d_in[24];
    float* out = (float*)d_out;

    cudaFuncSetAttribute(enc_kernel, cudaFuncAttributeMaxDynamicSharedMemorySize, ENC_SMEM_BYTES);
    cudaFuncSetAttribute(dec_kernel, cudaFuncAttributeMaxDynamicSharedMemorySize, DEC_SMEM_BYTES);

    prep_kernel<<<27, 128>>>(encWih, encBih, decWih, decBih,
                             embW, embB, projW, projB, gatW);

    enc_kernel<<<BNq / 128, 128, ENC_SMEM_BYTES>>>(x, encWhh, encBhh, attSrc, attDst);

    gat_kernel<<<BNq / 128, 128>>>(gatB, cW1, cB1, cW2, cB2, out);

    dec_kernel<<<BNq / 128, 128, DEC_SMEM_BYTES>>>(x, decWhh, decBhh,
                                                   oW1, oB1, oW2, oB2, out);
}

// round 3
// speedup vs baseline: 1.4702x; 1.4702x over previous
#include <cuda_runtime.h>
#include <cstdint>

// ---------------------------------------------------------------------------
// Model_78898549227585: embed -> GRU encoder (T=5) -> GATConv -> GRUCell
// decoder (T_OUT=6, autoregressive) + confidence head.
// B=32768, N=5, H=64, F=10, M=5.  Packed fp32x2 (fma.rn.f32x2) everywhere.
// ---------------------------------------------------------------------------

#define DINL __device__ __forceinline__

typedef unsigned long long u64;

constexpr int Bq   = 32768;
constexpr int Tq   = 5;
constexpr int Nq   = 5;
constexpr int Fq   = 10;
constexpr int Hq   = 64;
constexpr int Gq   = 192;   // 3H
constexpr int Mq   = 5;
constexpr int TOq  = 6;
constexpr int BNq  = Bq * Nq;                       // 163840
constexpr long long TRAJ_ELEMS = (long long)Bq * Mq * Nq * TOq * 2;  // 9,830,400

// ------------------------- device scratch ---------------------------------
__device__ float g_Wc_enc[Gq * Fq];
__device__ float g_bc_enc[Gq];
__device__ float g_Wc_dec[Gq * 2];
__device__ float g_bc_dec[Gq];
__device__ float g_Wc_xl[Fq * Hq];
__device__ float g_b_xl[Hq];

__device__ __align__(16) float g_henc[(size_t)BNq * Hq];
__device__ __align__(16) float g_xl  [(size_t)BNq * Hq];
__device__ float g_as  [BNq];
__device__ float g_ad  [BNq];
__device__ int   g_mask[BNq];
__device__ __align__(16) float g_hfin[(size_t)BNq * Hq];

// ------------------------- packed helpers ----------------------------------
DINL u64 fma2(u64 a, u64 b, u64 c) {
    u64 d; asm("fma.rn.f32x2 %0,%1,%2,%3;" : "=l"(d) : "l"(a), "l"(b), "l"(c));
    return d;
}
DINL u64 add2(u64 a, u64 b) {
    u64 d; asm("add.rn.f32x2 %0,%1,%2;" : "=l"(d) : "l"(a), "l"(b));
    return d;
}
DINL float2 unpk(u64 v) {
    float2 f; asm("mov.b64 {%0,%1},%2;" : "=f"(f.x), "=f"(f.y) : "l"(v));
    return f;
}
DINL u64 pk(float lo, float hi) {
    u64 v; asm("mov.b64 %0,{%1,%2};" : "=l"(v) : "f"(lo), "f"(hi));
    return v;
}
DINL float hadd(u64 v) { float2 f = unpk(v); return f.x + f.y; }
DINL u64 bc2(float x)  { return pk(x, x); }

DINL float sigmf(float v)  { return __fdividef(1.f, 1.f + __expf(-v)); }
DINL float tanhf_(float v) { return 1.f - __fdividef(2.f, __expf(2.f * v) + 1.f); }

// ------------------------- prep: fold weights ------------------------------
__global__ void prep_kernel(const float* __restrict__ enc_Wih,
                            const float* __restrict__ enc_bih,
                            const float* __restrict__ dec_Wih,
                            const float* __restrict__ dec_bih,
                            const float* __restrict__ embW,
                            const float* __restrict__ embB,
                            const float* __restrict__ projW,
                            const float* __restrict__ projB,
                            const float* __restrict__ gatW)
{
    int t = blockIdx.x * blockDim.x + threadIdx.x;
    if (t < Gq * Fq) {                                   // 0..1919
        int j = t / Fq, c = t % Fq;
        float s = 0.f;
        for (int k = 0; k < Hq; k++) s += enc_Wih[j * Hq + k] * embW[c * Hq + k];
        g_Wc_enc[j * Fq + c] = s;
    } else if (t < 1920 + 192) {                         // bc_enc
        int j = t - 1920;
        float s = enc_bih[j];
        for (int k = 0; k < Hq; k++) s += enc_Wih[j * Hq + k] * embB[k];
        g_bc_enc[j] = s;
    } else if (t < 2112 + 384) {                         // Wc_dec
        int i = t - 2112;
        int j = i / 2, c = i % 2;
        float s = 0.f;
        for (int k = 0; k < Hq; k++) s += dec_Wih[j * Hq + k] * projW[c * Hq + k];
        g_Wc_dec[j * 2 + c] = s;
    } else if (t < 2496 + 192) {                         // bc_dec
        int j = t - 2496;
        float s = dec_bih[j];
        for (int k = 0; k < Hq; k++) s += dec_Wih[j * Hq + k] * projB[k];
        g_bc_dec[j] = s;
    } else if (t < 2688 + 640) {                         // Wc_xl
        int i = t - 2688;
        int c = i / Hq, k2 = i % Hq;
        float s = 0.f;
        for (int k = 0; k < Hq; k++) s += embW[c * Hq + k] * gatW[k * Hq + k2];
        g_Wc_xl[c * Hq + k2] = s;
    } else if (t < 3328 + 64) {                          // b_xl
        int k2 = t - 3328;
        float s = 0.f;
        for (int k = 0; k < Hq; k++) s += embB[k] * gatW[k * Hq + k2];
        g_b_xl[k2] = s;
    }
}

// ------------------------- encoder ------------------------------------------
// smem floats:
//  sWhh 12288 | sBhh 192 | sWc 2304 (stride 12) | sBc 192 | sWxl 640 |
//  sBxl 64 | sAs 64 | sAd 64 | hs 8192
constexpr int E_WHH = 0;
constexpr int E_BHH = 12288;
constexpr int E_WC  = 12480;
constexpr int E_BC  = 14784;
constexpr int E_WXL = 14976;
constexpr int E_BXL = 15616;
constexpr int E_AS  = 15680;
constexpr int E_AD  = 15744;
constexpr int E_HS  = 15808;
constexpr int ENC_SMEM_FLOATS = E_HS + 64 * 128;   // 24000
constexpr int ENC_SMEM_BYTES  = ENC_SMEM_FLOATS * 4;

__global__ void __launch_bounds__(128) enc_kernel(
    const float* __restrict__ x,
    const float* __restrict__ Whh,
    const float* __restrict__ bhh,
    const float* __restrict__ asrc,
    const float* __restrict__ adst)
{
    extern __shared__ float sm[];
    float* sWhh = sm + E_WHH;
    float* sBhh = sm + E_BHH;
    float* sWc  = sm + E_WC;
    float* sBc  = sm + E_BC;
    float* sWxl = sm + E_WXL;
    float* sBxl = sm + E_BXL;
    float* sAs  = sm + E_AS;
    float* sAd  = sm + E_AD;
    u64*   hsu  = reinterpret_cast<u64*>(sm + E_HS);

    const int tid = threadIdx.x;
    for (int i = tid; i < 12288; i += 128) sWhh[i] = Whh[i];
    for (int i = tid; i < 192;   i += 128) sBhh[i] = bhh[i];
    for (int i = tid; i < 2304;  i += 128) {
        int j = i / 12, c = i % 12;
        sWc[i] = (c < 10) ? g_Wc_enc[j * 10 + c] : 0.f;
    }
    for (int i = tid; i < 192;   i += 128) sBc[i]  = g_bc_enc[i];
    for (int i = tid; i < 640;   i += 128) sWxl[i] = g_Wc_xl[i];
    if (tid < 64) { sBxl[tid] = g_b_xl[tid]; sAs[tid] = asrc[tid]; sAd[tid] = adst[tid]; }
    __syncthreads();

    const int bn = blockIdx.x * 128 + tid;
    const int b  = bn / Nq;
    const int n  = bn % Nq;
    const float* xp = x + ((size_t)b * (Tq * Nq) + n) * Fq;

    u64 h2[32];
    #pragma unroll
    for (int k = 0; k < 32; k++) { h2[k] = 0ULL; hsu[k * 128 + tid] = 0ULL; }

    float x10[10];
    u64 xq5[5];

    for (int t = 0; t < Tq; t++) {
        const float2* xp2 = reinterpret_cast<const float2*>(xp + (size_t)t * (Nq * Fq));
        #pragma unroll
        for (int c2 = 0; c2 < 5; c2++) {
            float2 v = xp2[c2];
            x10[2 * c2] = v.x; x10[2 * c2 + 1] = v.y;
            xq5[c2] = pk(v.x, v.y);
        }

        #pragma unroll 1
        for (int jj = 0; jj < 32; jj++) {
            const int j = 2 * jj;
            const ulonglong2* wh0 = (const ulonglong2*)(sWhh + j * 64);
            const ulonglong2* wh1 = (const ulonglong2*)(sWhh + (j + 1) * 64);
            const ulonglong2* wh2 = (const ulonglong2*)(sWhh + (j + 64) * 64);
            const ulonglong2* wh3 = (const ulonglong2*)(sWhh + (j + 65) * 64);
            const ulonglong2* wh4 = (const ulonglong2*)(sWhh + (j + 128) * 64);
            const ulonglong2* wh5 = (const ulonglong2*)(sWhh + (j + 129) * 64);
            u64 r0 = 0, r1 = 0, z0 = 0, z1 = 0, n0 = 0, n1 = 0;
            #pragma unroll
            for (int k4 = 0; k4 < 16; k4++) {
                u64 ha = h2[2 * k4], hb = h2[2 * k4 + 1];
                ulonglong2 w;
                w = wh0[k4]; r0 = fma2(w.x, ha, r0); r0 = fma2(w.y, hb, r0);
                w = wh1[k4]; r1 = fma2(w.x, ha, r1); r1 = fma2(w.y, hb, r1);
                w = wh2[k4]; z0 = fma2(w.x, ha, z0); z0 = fma2(w.y, hb, z0);
                w = wh3[k4]; z1 = fma2(w.x, ha, z1); z1 = fma2(w.y, hb, z1);
                w = wh4[k4]; n0 = fma2(w.x, ha, n0); n0 = fma2(w.y, hb, n0);
                w = wh5[k4]; n1 = fma2(w.x, ha, n1); n1 = fma2(w.y, hb, n1);
            }
            // x-path (fold r,z into same accumulators; n kept separate)
            const u64* cx0 = (const u64*)(sWc + j * 12);
            const u64* cx1 = (const u64*)(sWc + (j + 1) * 12);
            const u64* cx2 = (const u64*)(sWc + (j + 64) * 12);
            const u64* cx3 = (const u64*)(sWc + (j + 65) * 12);
            const u64* cx4 = (const u64*)(sWc + (j + 128) * 12);
            const u64* cx5 = (const u64*)(sWc + (j + 129) * 12);
            u64 xn0 = 0, xn1 = 0;
            #pragma unroll
            for (int c2 = 0; c2 < 5; c2++) {
                u64 xv = xq5[c2];
                r0  = fma2(cx0[c2], xv, r0);
                r1  = fma2(cx1[c2], xv, r1);
                z0  = fma2(cx2[c2], xv, z0);
                z1  = fma2(cx3[c2], xv, z1);
                xn0 = fma2(cx4[c2], xv, xn0);
                xn1 = fma2(cx5[c2], xv, xn1);
            }
            float R0 = sigmf(hadd(r0) + sBhh[j]      + sBc[j]);
            float R1 = sigmf(hadd(r1) + sBhh[j + 1]  + sBc[j + 1]);
            float Z0 = sigmf(hadd(z0) + sBhh[j + 64] + sBc[j + 64]);
            float Z1 = sigmf(hadd(z1) + sBhh[j + 65] + sBc[j + 65]);
            float A0 = hadd(n0)  + sBhh[j + 128];
            float A1 = hadd(n1)  + sBhh[j + 129];
            float X0 = hadd(xn0) + sBc[j + 128];
            float X1 = hadd(xn1) + sBc[j + 129];
            float N0 = tanhf_(X0 + R0 * A0);
            float N1 = tanhf_(X1 + R1 * A1);
            float2 ho = unpk(hsu[jj * 128 + tid]);
            float hn0 = (1.f - Z0) * N0 + Z0 * ho.x;
            float hn1 = (1.f - Z1) * N1 + Z1 * ho.y;
            hsu[jj * 128 + tid] = pk(hn0, hn1);
        }
        #pragma unroll
        for (int k = 0; k < 32; k++) h2[k] = hsu[k * 128 + tid];
    }

    // store h_enc
    u64* ghe = reinterpret_cast<u64*>(g_henc) + (size_t)bn * 32;
    #pragma unroll
    for (int k = 0; k < 32; k++) ghe[k] = h2[k];

    // mask from last frame
    float s6 = x10[0] + x10[1] + x10[2] + x10[3] + x10[4] + x10[5];
    g_mask[bn] = (s6 != 0.f) ? 1 : 0;

    // GAT transformed features + attention scalars (packed over k)
    u64 xb[10];
    #pragma unroll
    for (int c = 0; c < 10; c++) xb[c] = bc2(x10[c]);
    const u64* bxl2 = (const u64*)sBxl;
    const u64* asp  = (const u64*)sAs;
    const u64* adp  = (const u64*)sAd;
    u64* gxl = reinterpret_cast<u64*>(g_xl) + (size_t)bn * 32;
    u64 asum = 0, adsum = 0;
    #pragma unroll 2
    for (int k2 = 0; k2 < 32; k2++) {
        u64 acc = bxl2[k2];
        #pragma unroll
        for (int c = 0; c < 10; c++)
            acc = fma2(xb[c], *((const u64*)(sWxl + c * 64) + k2), acc);
        gxl[k2] = acc;
        asum  = fma2(acc, asp[k2], asum);
        adsum = fma2(acc, adp[k2], adsum);
    }
    g_as[bn] = hadd(asum);
    g_ad[bn] = hadd(adsum);
}

// ------------------------- GAT + conf ---------------------------------------
__global__ void __launch_bounds__(128) gat_kernel(
    const float* __restrict__ gat_b,
    const float* __restrict__ cW1,
    const float* __restrict__ cB1,
    const float* __restrict__ cW2,
    const float* __restrict__ cB2,
    float* __restrict__ out)
{
    __shared__ __align__(16) float sW1t[4096];   // [m][k]
    __shared__ __align__(16) float sB1[64];
    __shared__ __align__(16) float sW2[512];     // [m][p] padded stride 8
    __shared__ __align__(16) float sB2[8];
    __shared__ __align__(16) float sGb[64];

    const int tid = threadIdx.x;
    for (int i = tid; i < 4096; i += 128) {
        int m = i >> 6, k = i & 63;
        sW1t[i] = cW1[k * 64 + m];
    }
    for (int i = tid; i < 512; i += 128) {
        int m = i >> 3, p = i & 7;
        sW2[i] = (p < 5) ? cW2[m * 5 + p] : 0.f;
    }
    if (tid < 64) { sB1[tid] = cB1[tid]; sGb[tid] = gat_b[tid]; }
    if (tid < 8)  sB2[tid] = (tid < 5) ? cB2[tid] : 0.f;
    __syncthreads();

    const int bn = blockIdx.x * 128 + tid;
    const int b  = bn / Nq;
    const int n  = bn % Nq;
    const int base = b * Nq;

    float ad_i = g_ad[bn];
    int   mi   = g_mask[bn];

    float w[5];
    float amax = -1e30f;
    #pragma unroll
    for (int j = 0; j < 5; j++) {
        int src = base + j;
        float a = g_as[src] + ad_i;
        a = a > 0.f ? a : 0.2f * a;
        bool valid = (j == n) ? true : (mi && g_mask[src]);
        w[j] = valid ? a : -1e30f;
        amax = fmaxf(amax, w[j]);
    }
    float denom = 0.f;
    #pragma unroll
    for (int j = 0; j < 5; j++) {
        float e = __expf(w[j] - amax);
        w[j] = e;
        denom += e;
    }
    float inv = __fdividef(1.f, denom);
    #pragma unroll
    for (int j = 0; j < 5; j++) w[j] *= inv;

    u64 acc2[32];
    #pragma unroll
    for (int k = 0; k < 32; k++) acc2[k] = 0ULL;
    #pragma unroll
    for (int j = 0; j < 5; j++) {
        const u64* xr = reinterpret_cast<const u64*>(g_xl) + (size_t)(base + j) * 32;
        u64 wj = bc2(w[j]);
        #pragma unroll
        for (int k = 0; k < 32; k++) acc2[k] = fma2(wj, xr[k], acc2[k]);
    }

    u64 hfp[32];
    const u64* he = reinterpret_cast<const u64*>(g_henc) + (size_t)bn * 32;
    const u64* gb = (const u64*)sGb;
    u64* hfo = reinterpret_cast<u64*>(g_hfin) + (size_t)bn * 32;
    #pragma unroll
    for (int k = 0; k < 32; k++) {
        u64 r = add2(add2(he[k], acc2[k]), gb[k]);
        hfp[k] = r;
        hfo[k] = r;
    }

    // conf head (packed)
    u64 o2p[3];
    o2p[0] = pk(sB2[0], sB2[1]);
    o2p[1] = pk(sB2[2], sB2[3]);
    o2p[2] = pk(sB2[4], 0.f);
    #pragma unroll 2
    for (int m = 0; m < 64; m++) {
        const ulonglong2* w1 = (const ulonglong2*)(sW1t + m * 64);
        u64 acc = 0;
        #pragma unroll
        for (int k4 = 0; k4 < 16; k4++) {
            ulonglong2 wv = w1[k4];
            acc = fma2(wv.x, hfp[2 * k4], acc);
            acc = fma2(wv.y, hfp[2 * k4 + 1], acc);
        }
        float t = fmaxf(hadd(acc) + sB1[m], 0.f);
        u64 t2 = bc2(t);
        const u64* w2r = (const u64*)(sW2 + m * 8);
        o2p[0] = fma2(t2, w2r[0], o2p[0]);
        o2p[1] = fma2(t2, w2r[1], o2p[1]);
        o2p[2] = fma2(t2, w2r[2], o2p[2]);
    }
    float o[5];
    { float2 a = unpk(o2p[0]); o[0] = a.x; o[1] = a.y; }
    { float2 a = unpk(o2p[1]); o[2] = a.x; o[3] = a.y; }
    { float2 a = unpk(o2p[2]); o[4] = a.x; }
    float mx = o[0];
    #pragma unroll
    for (int p = 1; p < 5; p++) mx = fmaxf(mx, o[p]);
    float s = 0.f;
    #pragma unroll
    for (int p = 0; p < 5; p++) { o[p] = __expf(o[p] - mx); s += o[p]; }
    float invs = __fdividef(1.f, s);

    float* conf = out + TRAJ_ELEMS;
    #pragma unroll
    for (int p = 0; p < 5; p++)
        conf[(size_t)b * 25 + p * 5 + n] = o[p] * invs;
}

// ------------------------- decoder ------------------------------------------
// smem floats:
//  sWhh 12288 | sBhh 192 | sWcd 384 | sBcd 192 | sW1t 4096 | sB1 64 |
//  sW2p 768 (stride 12) | sB2 16 | hs 8192
constexpr int D_WHH = 0;
constexpr int D_BHH = 12288;
constexpr int D_WCD = 12480;
constexpr int D_BCD = 12864;
constexpr int D_W1T = 13056;
constexpr int D_B1  = 17152;
constexpr int D_W2  = 17216;
constexpr int D_B2  = 17984;
constexpr int D_HS  = 18000;
constexpr int DEC_SMEM_FLOATS = D_HS + 64 * 128;   // 26192
constexpr int DEC_SMEM_BYTES  = DEC_SMEM_FLOATS * 4;

__global__ void __launch_bounds__(128) dec_kernel(
    const float* __restrict__ x,
    const float* __restrict__ Whh,
    const float* __restrict__ bhh,
    const float* __restrict__ oW1,
    const float* __restrict__ oB1,
    const float* __restrict__ oW2,
    const float* __restrict__ oB2,
    float* __restrict__ out)
{
    extern __shared__ float sm[];
    float* sWhh = sm + D_WHH;
    float* sBhh = sm + D_BHH;
    float* sWcd = sm + D_WCD;
    float* sBcd = sm + D_BCD;
    float* sW1t = sm + D_W1T;
    float* sB1  = sm + D_B1;
    float* sW2p = sm + D_W2;
    float* sB2  = sm + D_B2;
    u64*   hsu  = reinterpret_cast<u64*>(sm + D_HS);

    const int tid = threadIdx.x;
    for (int i = tid; i < 12288; i += 128) sWhh[i] = Whh[i];
    for (int i = tid; i < 192;   i += 128) sBhh[i] = bhh[i];
    for (int i = tid; i < 384;   i += 128) sWcd[i] = g_Wc_dec[i];
    for (int i = tid; i < 192;   i += 128) sBcd[i] = g_bc_dec[i];
    for (int i = tid; i < 4096;  i += 128) {
        int m = i >> 6, k = i & 63;
        sW1t[i] = oW1[k * 64 + m];
    }
    for (int i = tid; i < 768;   i += 128) {
        int m = i / 12, c = i % 12;
        sW2p[i] = (c < 10) ? oW2[m * 10 + c] : 0.f;
    }
    if (tid < 64) sB1[tid] = oB1[tid];
    if (tid < 16) sB2[tid] = (tid < 10) ? oB2[tid] : 0.f;
    __syncthreads();

    const int bn = blockIdx.x * 128 + tid;
    const int b  = bn / Nq;
    const int n  = bn % Nq;

    u64 h2[32];
    const u64* hf = reinterpret_cast<const u64*>(g_hfin) + (size_t)bn * 32;
    #pragma unroll
    for (int k = 0; k < 32; k++) { h2[k] = hf[k]; hsu[k * 128 + tid] = h2[k]; }

    // last-frame xy
    const float* xl = x + ((size_t)b * (Tq * Nq) + 4 * Nq + n) * Fq;
    float xy0 = xl[0];
    float xy1 = xl[1];

    for (int t = 0; t < TOq; t++) {
        #pragma unroll 1
        for (int jj = 0; jj < 32; jj++) {
            const int j = 2 * jj;
            const ulonglong2* wh0 = (const ulonglong2*)(sWhh + j * 64);
            const ulonglong2* wh1 = (const ulonglong2*)(sWhh + (j + 1) * 64);
            const ulonglong2* wh2 = (const ulonglong2*)(sWhh + (j + 64) * 64);
            const ulonglong2* wh3 = (const ulonglong2*)(sWhh + (j + 65) * 64);
            const ulonglong2* wh4 = (const ulonglong2*)(sWhh + (j + 128) * 64);
            const ulonglong2* wh5 = (const ulonglong2*)(sWhh + (j + 129) * 64);
            u64 r0 = 0, r1 = 0, z0 = 0, z1 = 0, n0 = 0, n1 = 0;
            #pragma unroll
            for (int k4 = 0; k4 < 16; k4++) {
                u64 ha = h2[2 * k4], hb = h2[2 * k4 + 1];
                ulonglong2 w;
                w = wh0[k4]; r0 = fma2(w.x, ha, r0); r0 = fma2(w.y, hb, r0);
                w = wh1[k4]; r1 = fma2(w.x, ha, r1); r1 = fma2(w.y, hb, r1);
                w = wh2[k4]; z0 = fma2(w.x, ha, z0); z0 = fma2(w.y, hb, z0);
                w = wh3[k4]; z1 = fma2(w.x, ha, z1); z1 = fma2(w.y, hb, z1);
                w = wh4[k4]; n0 = fma2(w.x, ha, n0); n0 = fma2(w.y, hb, n0);
                w = wh5[k4]; n1 = fma2(w.x, ha, n1); n1 = fma2(w.y, hb, n1);
            }
            float xr0 = sBcd[j]       + sWcd[j * 2] * xy0         + sWcd[j * 2 + 1] * xy1;
            float xr1 = sBcd[j + 1]   + sWcd[(j + 1) * 2] * xy0   + sWcd[(j + 1) * 2 + 1] * xy1;
            float xz0 = sBcd[j + 64]  + sWcd[(j + 64) * 2] * xy0  + sWcd[(j + 64) * 2 + 1] * xy1;
            float xz1 = sBcd[j + 65]  + sWcd[(j + 65) * 2] * xy0  + sWcd[(j + 65) * 2 + 1] * xy1;
            float xn0 = sBcd[j + 128] + sWcd[(j + 128) * 2] * xy0 + sWcd[(j + 128) * 2 + 1] * xy1;
            float xn1 = sBcd[j + 129] + sWcd[(j + 129) * 2] * xy0 + sWcd[(j + 129) * 2 + 1] * xy1;
            float R0 = sigmf(hadd(r0) + sBhh[j]      + xr0);
            float R1 = sigmf(hadd(r1) + sBhh[j + 1]  + xr1);
            float Z0 = sigmf(hadd(z0) + sBhh[j + 64] + xz0);
            float Z1 = sigmf(hadd(z1) + sBhh[j + 65] + xz1);
            float A0 = hadd(n0) + sBhh[j + 128];
            float A1 = hadd(n1) + sBhh[j + 129];
            float N0 = tanhf_(xn0 + R0 * A0);
            float N1 = tanhf_(xn1 + R1 * A1);
            float2 ho = unpk(hsu[jj * 128 + tid]);
            float hn0 = (1.f - Z0) * N0 + Z0 * ho.x;
            float hn1 = (1.f - Z1) * N1 + Z1 * ho.y;
            hsu[jj * 128 + tid] = pk(hn0, hn1);
        }
        #pragma unroll
        for (int k = 0; k < 32; k++) h2[k] = hsu[k * 128 + tid];

        // out MLP: o2 = relu(h @ W1 + b1) @ W2 + b2, packed
        u64 o2p[5];
        #pragma unroll
        for (int p = 0; p < 5; p++) o2p[p] = pk(sB2[2 * p], sB2[2 * p + 1]);
        #pragma unroll 2
        for (int m = 0; m < 64; m++) {
            const ulonglong2* w1 = (const ulonglong2*)(sW1t + m * 64);
            u64 acc = 0;
            #pragma unroll
            for (int k4 = 0; k4 < 16; k4++) {
                ulonglong2 wv = w1[k4];
                acc = fma2(wv.x, h2[2 * k4], acc);
                acc = fma2(wv.y, h2[2 * k4 + 1], acc);
            }
            float a = fmaxf(hadd(acc) + sB1[m], 0.f);
            u64 a2 = bc2(a);
            const u64* w2r = (const u64*)(sW2p + m * 12);
            #pragma unroll
            for (int p = 0; p < 5; p++) o2p[p] = fma2(a2, w2r[p], o2p[p]);
        }
        float o[10];
        #pragma unroll
        for (int p = 0; p < 5; p++) {
            float2 v = unpk(o2p[p]);
            o[2 * p] = v.x; o[2 * p + 1] = v.y;
        }

        // traj[b, m, n, t, c] = o[c*5 + m]
        size_t ob = (size_t)b * 300 + (size_t)n * 12 + t * 2;
        #pragma unroll
        for (int m = 0; m < 5; m++) {
            out[ob + m * 60 + 0] = o[m];
            out[ob + m * 60 + 1] = o[5 + m];
        }
        xy0 = o[0];
        xy1 = o[5];
    }
}

// ------------------------- launch -------------------------------------------
extern "C" void kernel_launch(void* const* d_in, const int* in_sizes, int n_in,
                              void* d_out, int out_size)
{
    const float* x        = (const float*)d_in[0];
    const float* embW     = (const float*)d_in[1];
    const float* embB     = (const float*)d_in[2];
    const float* gatW     = (const float*)d_in[3];
    const float* attSrc   = (const float*)d_in[4];
    const float* attDst   = (const float*)d_in[5];
    const float* gatB     = (const float*)d_in[6];
    const float* encWih   = (const float*)d_in[7];
    const float* encWhh   = (const float*)d_in[8];
    const float* encBih   = (const float*)d_in[9];
    const float* encBhh   = (const float*)d_in[10];
    const float* decWih   = (const float*)d_in[11];
    const float* decWhh   = (const float*)d_in[12];
    const float* decBih   = (const float*)d_in[13];
    const float* decBhh   = (const float*)d_in[14];
    const float* oW1      = (const float*)d_in[15];
    const float* oB1      = (const float*)d_in[16];
    const float* oW2      = (const float*)d_in[17];
    const float* oB2      = (const float*)d_in[18];
    const float* projW    = (const float*)d_in[19];
    const float* projB    = (const float*)d_in[20];
    const float* cW1      = (const float*)d_in[21];
    const float* cB1      = (const float*)d_in[22];
    const float* cW2      = (const float*)d_in[23];
    const float* cB2      = (const float*)d_in[24];
    float* out = (float*)d_out;

    cudaFuncSetAttribute(enc_kernel, cudaFuncAttributeMaxDynamicSharedMemorySize, ENC_SMEM_BYTES);
    cudaFuncSetAttribute(dec_kernel, cudaFuncAttributeMaxDynamicSharedMemorySize, DEC_SMEM_BYTES);

    prep_kernel<<<27, 128>>>(encWih, encBih, decWih, decBih,
                             embW, embB, projW, projB, gatW);

    enc_kernel<<<BNq / 128, 128, ENC_SMEM_BYTES>>>(x, encWhh, encBhh, attSrc, attDst);

    gat_kernel<<<BNq / 128, 128>>>(gatB, cW1, cB1, cW2, cB2, out);

    dec_kernel<<<BNq / 128, 128, DEC_SMEM_BYTES>>>(x, decWhh, decBhh,
                                                   oW1, oB1, oW2, oB2, out);
}

// round 4
// speedup vs baseline: 1.4745x; 1.0029x over previous
#include <cuda_runtime.h>
#include <cstdint>

// ---------------------------------------------------------------------------
// Model_78898549227585: embed -> GRU encoder (T=5) -> GATConv -> GRUCell
// decoder (T_OUT=6, autoregressive) + confidence head.
// B=32768, N=5, H=64, F=10, M=5.  Packed fp32x2 (fma.rn.f32x2) everywhere.
// ---------------------------------------------------------------------------

#define DINL __device__ __forceinline__

typedef unsigned long long u64;

constexpr int Bq   = 32768;
constexpr int Tq   = 5;
constexpr int Nq   = 5;
constexpr int Fq   = 10;
constexpr int Hq   = 64;
constexpr int Gq   = 192;   // 3H
constexpr int Mq   = 5;
constexpr int TOq  = 6;
constexpr int BNq  = Bq * Nq;                       // 163840
constexpr long long TRAJ_ELEMS = (long long)Bq * Mq * Nq * TOq * 2;  // 9,830,400

// ------------------------- device scratch ---------------------------------
__device__ float g_Wc_enc[Gq * Fq];
__device__ float g_bc_enc[Gq];
__device__ float g_Wc_dec[Gq * 2];
__device__ float g_bc_dec[Gq];
__device__ float g_Wc_xl[Fq * Hq];
__device__ float g_b_xl[Hq];

__device__ __align__(16) float g_henc[(size_t)BNq * Hq];
__device__ __align__(16) float g_xl  [(size_t)BNq * Hq];
__device__ float g_as  [BNq];
__device__ float g_ad  [BNq];
__device__ int   g_mask[BNq];
__device__ __align__(16) float g_hfin[(size_t)BNq * Hq];

// ------------------------- packed helpers ----------------------------------
DINL u64 fma2(u64 a, u64 b, u64 c) {
    u64 d; asm("fma.rn.f32x2 %0,%1,%2,%3;" : "=l"(d) : "l"(a), "l"(b), "l"(c));
    return d;
}
DINL u64 add2(u64 a, u64 b) {
    u64 d; asm("add.rn.f32x2 %0,%1,%2;" : "=l"(d) : "l"(a), "l"(b));
    return d;
}
DINL float2 unpk(u64 v) {
    float2 f; asm("mov.b64 {%0,%1},%2;" : "=f"(f.x), "=f"(f.y) : "l"(v));
    return f;
}
DINL u64 pk(float lo, float hi) {
    u64 v; asm("mov.b64 %0,{%1,%2};" : "=l"(v) : "f"(lo), "f"(hi));
    return v;
}
DINL float hadd(u64 v) { float2 f = unpk(v); return f.x + f.y; }
DINL u64 bc2(float x)  { return pk(x, x); }

DINL float sigmf(float v)  { return __fdividef(1.f, 1.f + __expf(-v)); }
DINL float tanhf_(float v) { return 1.f - __fdividef(2.f, __expf(2.f * v) + 1.f); }

// ------------------------- prep: fold weights ------------------------------
__global__ void prep_kernel(const float* __restrict__ enc_Wih,
                            const float* __restrict__ enc_bih,
                            const float* __restrict__ dec_Wih,
                            const float* __restrict__ dec_bih,
                            const float* __restrict__ embW,
                            const float* __restrict__ embB,
                            const float* __restrict__ projW,
                            const float* __restrict__ projB,
                            const float* __restrict__ gatW)
{
    int t = blockIdx.x * blockDim.x + threadIdx.x;
    if (t < Gq * Fq) {                                   // 0..1919
        int j = t / Fq, c = t % Fq;
        float s = 0.f;
        for (int k = 0; k < Hq; k++) s += enc_Wih[j * Hq + k] * embW[c * Hq + k];
        g_Wc_enc[j * Fq + c] = s;
    } else if (t < 1920 + 192) {                         // bc_enc
        int j = t - 1920;
        float s = enc_bih[j];
        for (int k = 0; k < Hq; k++) s += enc_Wih[j * Hq + k] * embB[k];
        g_bc_enc[j] = s;
    } else if (t < 2112 + 384) {                         // Wc_dec
        int i = t - 2112;
        int j = i / 2, c = i % 2;
        float s = 0.f;
        for (int k = 0; k < Hq; k++) s += dec_Wih[j * Hq + k] * projW[c * Hq + k];
        g_Wc_dec[j * 2 + c] = s;
    } else if (t < 2496 + 192) {                         // bc_dec
        int j = t - 2496;
        float s = dec_bih[j];
        for (int k = 0; k < Hq; k++) s += dec_Wih[j * Hq + k] * projB[k];
        g_bc_dec[j] = s;
    } else if (t < 2688 + 640) {                         // Wc_xl
        int i = t - 2688;
        int c = i / Hq, k2 = i % Hq;
        float s = 0.f;
        for (int k = 0; k < Hq; k++) s += embW[c * Hq + k] * gatW[k * Hq + k2];
        g_Wc_xl[c * Hq + k2] = s;
    } else if (t < 3328 + 64) {                          // b_xl
        int k2 = t - 3328;
        float s = 0.f;
        for (int k = 0; k < Hq; k++) s += embB[k] * gatW[k * Hq + k2];
        g_b_xl[k2] = s;
    }
}

// ------------------------- encoder ------------------------------------------
// smem floats:
//  sWhh 12288 | sBhh 192 | sWc 2304 (stride 12) | sBc 192 | sWxl 640 |
//  sBxl 64 | sAs 64 | sAd 64 | hs 8192
constexpr int E_WHH = 0;
constexpr int E_BHH = 12288;
constexpr int E_WC  = 12480;
constexpr int E_BC  = 14784;
constexpr int E_WXL = 14976;
constexpr int E_BXL = 15616;
constexpr int E_AS  = 15680;
constexpr int E_AD  = 15744;
constexpr int E_HS  = 15808;
constexpr int ENC_SMEM_FLOATS = E_HS + 64 * 128;   // 24000
constexpr int ENC_SMEM_BYTES  = ENC_SMEM_FLOATS * 4;

__global__ void __launch_bounds__(128) enc_kernel(
    const float* __restrict__ x,
    const float* __restrict__ Whh,
    const float* __restrict__ bhh,
    const float* __restrict__ asrc,
    const float* __restrict__ adst)
{
    extern __shared__ float sm[];
    float* sWhh = sm + E_WHH;
    float* sBhh = sm + E_BHH;
    float* sWc  = sm + E_WC;
    float* sBc  = sm + E_BC;
    float* sWxl = sm + E_WXL;
    float* sBxl = sm + E_BXL;
    float* sAs  = sm + E_AS;
    float* sAd  = sm + E_AD;
    u64*   hsu  = reinterpret_cast<u64*>(sm + E_HS);

    const int tid = threadIdx.x;
    for (int i = tid; i < 12288; i += 128) sWhh[i] = Whh[i];
    for (int i = tid; i < 192;   i += 128) sBhh[i] = bhh[i];
    for (int i = tid; i < 2304;  i += 128) {
        int j = i / 12, c = i % 12;
        sWc[i] = (c < 10) ? g_Wc_enc[j * 10 + c] : 0.f;
    }
    for (int i = tid; i < 192;   i += 128) sBc[i]  = g_bc_enc[i];
    for (int i = tid; i < 640;   i += 128) sWxl[i] = g_Wc_xl[i];
    if (tid < 64) { sBxl[tid] = g_b_xl[tid]; sAs[tid] = asrc[tid]; sAd[tid] = adst[tid]; }
    __syncthreads();

    const int bn = blockIdx.x * 128 + tid;
    const int b  = bn / Nq;
    const int n  = bn % Nq;
    const float* xp = x + ((size_t)b * (Tq * Nq) + n) * Fq;

    u64 h2[32];
    #pragma unroll
    for (int k = 0; k < 32; k++) { h2[k] = 0ULL; hsu[k * 128 + tid] = 0ULL; }

    float x10[10];
    u64 xq5[5];

    for (int t = 0; t < Tq; t++) {
        const float2* xp2 = reinterpret_cast<const float2*>(xp + (size_t)t * (Nq * Fq));
        #pragma unroll
        for (int c2 = 0; c2 < 5; c2++) {
            float2 v = xp2[c2];
            x10[2 * c2] = v.x; x10[2 * c2 + 1] = v.y;
            xq5[c2] = pk(v.x, v.y);
        }

        #pragma unroll 1
        for (int jj = 0; jj < 32; jj++) {
            const int j = 2 * jj;
            const ulonglong2* wh0 = (const ulonglong2*)(sWhh + j * 64);
            const ulonglong2* wh1 = (const ulonglong2*)(sWhh + (j + 1) * 64);
            const ulonglong2* wh2 = (const ulonglong2*)(sWhh + (j + 64) * 64);
            const ulonglong2* wh3 = (const ulonglong2*)(sWhh + (j + 65) * 64);
            const ulonglong2* wh4 = (const ulonglong2*)(sWhh + (j + 128) * 64);
            const ulonglong2* wh5 = (const ulonglong2*)(sWhh + (j + 129) * 64);
            u64 r0 = 0, r1 = 0, z0 = 0, z1 = 0, n0 = 0, n1 = 0;
            #pragma unroll
            for (int k4 = 0; k4 < 16; k4++) {
                u64 ha = h2[2 * k4], hb = h2[2 * k4 + 1];
                ulonglong2 w;
                w = wh0[k4]; r0 = fma2(w.x, ha, r0); r0 = fma2(w.y, hb, r0);
                w = wh1[k4]; r1 = fma2(w.x, ha, r1); r1 = fma2(w.y, hb, r1);
                w = wh2[k4]; z0 = fma2(w.x, ha, z0); z0 = fma2(w.y, hb, z0);
                w = wh3[k4]; z1 = fma2(w.x, ha, z1); z1 = fma2(w.y, hb, z1);
                w = wh4[k4]; n0 = fma2(w.x, ha, n0); n0 = fma2(w.y, hb, n0);
                w = wh5[k4]; n1 = fma2(w.x, ha, n1); n1 = fma2(w.y, hb, n1);
            }
            // x-path (fold r,z into same accumulators; n kept separate)
            const u64* cx0 = (const u64*)(sWc + j * 12);
            const u64* cx1 = (const u64*)(sWc + (j + 1) * 12);
            const u64* cx2 = (const u64*)(sWc + (j + 64) * 12);
            const u64* cx3 = (const u64*)(sWc + (j + 65) * 12);
            const u64* cx4 = (const u64*)(sWc + (j + 128) * 12);
            const u64* cx5 = (const u64*)(sWc + (j + 129) * 12);
            u64 xn0 = 0, xn1 = 0;
            #pragma unroll
            for (int c2 = 0; c2 < 5; c2++) {
                u64 xv = xq5[c2];
                r0  = fma2(cx0[c2], xv, r0);
                r1  = fma2(cx1[c2], xv, r1);
                z0  = fma2(cx2[c2], xv, z0);
                z1  = fma2(cx3[c2], xv, z1);
                xn0 = fma2(cx4[c2], xv, xn0);
                xn1 = fma2(cx5[c2], xv, xn1);
            }
            float R0 = sigmf(hadd(r0) + sBhh[j]      + sBc[j]);
            float R1 = sigmf(hadd(r1) + sBhh[j + 1]  + sBc[j + 1]);
            float Z0 = sigmf(hadd(z0) + sBhh[j + 64] + sBc[j + 64]);
            float Z1 = sigmf(hadd(z1) + sBhh[j + 65] + sBc[j + 65]);
            float A0 = hadd(n0)  + sBhh[j + 128];
            float A1 = hadd(n1)  + sBhh[j + 129];
            float X0 = hadd(xn0) + sBc[j + 128];
            float X1 = hadd(xn1) + sBc[j + 129];
            float N0 = tanhf_(X0 + R0 * A0);
            float N1 = tanhf_(X1 + R1 * A1);
            float2 ho = unpk(hsu[jj * 128 + tid]);
            float hn0 = (1.f - Z0) * N0 + Z0 * ho.x;
            float hn1 = (1.f - Z1) * N1 + Z1 * ho.y;
            hsu[jj * 128 + tid] = pk(hn0, hn1);
        }
        #pragma unroll
        for (int k = 0; k < 32; k++) h2[k] = hsu[k * 128 + tid];
    }

    // store h_enc
    u64* ghe = reinterpret_cast<u64*>(g_henc) + (size_t)bn * 32;
    #pragma unroll
    for (int k = 0; k < 32; k++) ghe[k] = h2[k];

    // mask from last frame
    float s6 = x10[0] + x10[1] + x10[2] + x10[3] + x10[4] + x10[5];
    g_mask[bn] = (s6 != 0.f) ? 1 : 0;

    // GAT transformed features + attention scalars (packed over k)
    u64 xb[10];
    #pragma unroll
    for (int c = 0; c < 10; c++) xb[c] = bc2(x10[c]);
    const u64* bxl2 = (const u64*)sBxl;
    const u64* asp  = (const u64*)sAs;
    const u64* adp  = (const u64*)sAd;
    u64* gxl = reinterpret_cast<u64*>(g_xl) + (size_t)bn * 32;
    u64 asum = 0, adsum = 0;
    #pragma unroll 2
    for (int k2 = 0; k2 < 32; k2++) {
        u64 acc = bxl2[k2];
        #pragma unroll
        for (int c = 0; c < 10; c++)
            acc = fma2(xb[c], *((const u64*)(sWxl + c * 64) + k2), acc);
        gxl[k2] = acc;
        asum  = fma2(acc, asp[k2], asum);
        adsum = fma2(acc, adp[k2], adsum);
    }
    g_as[bn] = hadd(asum);
    g_ad[bn] = hadd(adsum);
}

// ------------------------- GAT + conf ---------------------------------------
__global__ void __launch_bounds__(128) gat_kernel(
    const float* __restrict__ gat_b,
    const float* __restrict__ cW1,
    const float* __restrict__ cB1,
    const float* __restrict__ cW2,
    const float* __restrict__ cB2,
    float* __restrict__ out)
{
    __shared__ __align__(16) float sW1t[4096];   // [m][k]
    __shared__ __align__(16) float sB1[64];
    __shared__ __align__(16) float sW2[512];     // [m][p] padded stride 8
    __shared__ __align__(16) float sB2[8];
    __shared__ __align__(16) float sGb[64];

    const int tid = threadIdx.x;
    for (int i = tid; i < 4096; i += 128) {
        int m = i >> 6, k = i & 63;
        sW1t[i] = cW1[k * 64 + m];
    }
    for (int i = tid; i < 512; i += 128) {
        int m = i >> 3, p = i & 7;
        sW2[i] = (p < 5) ? cW2[m * 5 + p] : 0.f;
    }
    if (tid < 64) { sB1[tid] = cB1[tid]; sGb[tid] = gat_b[tid]; }
    if (tid < 8)  sB2[tid] = (tid < 5) ? cB2[tid] : 0.f;
    __syncthreads();

    const int bn = blockIdx.x * 128 + tid;
    const int b  = bn / Nq;
    const int n  = bn % Nq;
    const int base = b * Nq;

    float ad_i = g_ad[bn];
    int   mi   = g_mask[bn];

    float w[5];
    float amax = -1e30f;
    #pragma unroll
    for (int j = 0; j < 5; j++) {
        int src = base + j;
        float a = g_as[src] + ad_i;
        a = a > 0.f ? a : 0.2f * a;
        bool valid = (j == n) ? true : (mi && g_mask[src]);
        w[j] = valid ? a : -1e30f;
        amax = fmaxf(amax, w[j]);
    }
    float denom = 0.f;
    #pragma unroll
    for (int j = 0; j < 5; j++) {
        float e = __expf(w[j] - amax);
        w[j] = e;
        denom += e;
    }
    float inv = __fdividef(1.f, denom);
    #pragma unroll
    for (int j = 0; j < 5; j++) w[j] *= inv;

    u64 acc2[32];
    #pragma unroll
    for (int k = 0; k < 32; k++) acc2[k] = 0ULL;
    #pragma unroll
    for (int j = 0; j < 5; j++) {
        const u64* xr = reinterpret_cast<const u64*>(g_xl) + (size_t)(base + j) * 32;
        u64 wj = bc2(w[j]);
        #pragma unroll
        for (int k = 0; k < 32; k++) acc2[k] = fma2(wj, xr[k], acc2[k]);
    }

    u64 hfp[32];
    const u64* he = reinterpret_cast<const u64*>(g_henc) + (size_t)bn * 32;
    const u64* gb = (const u64*)sGb;
    u64* hfo = reinterpret_cast<u64*>(g_hfin) + (size_t)bn * 32;
    #pragma unroll
    for (int k = 0; k < 32; k++) {
        u64 r = add2(add2(he[k], acc2[k]), gb[k]);
        hfp[k] = r;
        hfo[k] = r;
    }

    // conf head (packed)
    u64 o2p[3];
    o2p[0] = pk(sB2[0], sB2[1]);
    o2p[1] = pk(sB2[2], sB2[3]);
    o2p[2] = pk(sB2[4], 0.f);
    #pragma unroll 2
    for (int m = 0; m < 64; m++) {
        const ulonglong2* w1 = (const ulonglong2*)(sW1t + m * 64);
        u64 acc = 0;
        #pragma unroll
        for (int k4 = 0; k4 < 16; k4++) {
            ulonglong2 wv = w1[k4];
            acc = fma2(wv.x, hfp[2 * k4], acc);
            acc = fma2(wv.y, hfp[2 * k4 + 1], acc);
        }
        float t = fmaxf(hadd(acc) + sB1[m], 0.f);
        u64 t2 = bc2(t);
        const u64* w2r = (const u64*)(sW2 + m * 8);
        o2p[0] = fma2(t2, w2r[0], o2p[0]);
        o2p[1] = fma2(t2, w2r[1], o2p[1]);
        o2p[2] = fma2(t2, w2r[2], o2p[2]);
    }
    float o[5];
    { float2 a = unpk(o2p[0]); o[0] = a.x; o[1] = a.y; }
    { float2 a = unpk(o2p[1]); o[2] = a.x; o[3] = a.y; }
    { float2 a = unpk(o2p[2]); o[4] = a.x; }
    float mx = o[0];
    #pragma unroll
    for (int p = 1; p < 5; p++) mx = fmaxf(mx, o[p]);
    float s = 0.f;
    #pragma unroll
    for (int p = 0; p < 5; p++) { o[p] = __expf(o[p] - mx); s += o[p]; }
    float invs = __fdividef(1.f, s);

    float* conf = out + TRAJ_ELEMS;
    #pragma unroll
    for (int p = 0; p < 5; p++)
        conf[(size_t)b * 25 + p * 5 + n] = o[p] * invs;
}

// ------------------------- decoder ------------------------------------------
// smem floats:
//  sWhh 12288 | sBhh 192 | sWcd 384 | sBcd 192 | sW1t 4096 | sB1 64 |
//  sW2p 768 (stride 12) | sB2 16 | hs 8192
constexpr int D_WHH = 0;
constexpr int D_BHH = 12288;
constexpr int D_WCD = 12480;
constexpr int D_BCD = 12864;
constexpr int D_W1T = 13056;
constexpr int D_B1  = 17152;
constexpr int D_W2  = 17216;
constexpr int D_B2  = 17984;
constexpr int D_HS  = 18000;
constexpr int DEC_SMEM_FLOATS = D_HS + 64 * 128;   // 26192
constexpr int DEC_SMEM_BYTES  = DEC_SMEM_FLOATS * 4;

__global__ void __launch_bounds__(128) dec_kernel(
    const float* __restrict__ x,
    const float* __restrict__ Whh,
    const float* __restrict__ bhh,
    const float* __restrict__ oW1,
    const float* __restrict__ oB1,
    const float* __restrict__ oW2,
    const float* __restrict__ oB2,
    float* __restrict__ out)
{
    extern __shared__ float sm[];
    float* sWhh = sm + D_WHH;
    float* sBhh = sm + D_BHH;
    float* sWcd = sm + D_WCD;
    float* sBcd = sm + D_BCD;
    float* sW1t = sm + D_W1T;
    float* sB1  = sm + D_B1;
    float* sW2p = sm + D_W2;
    float* sB2  = sm + D_B2;
    u64*   hsu  = reinterpret_cast<u64*>(sm + D_HS);

    const int tid = threadIdx.x;
    for (int i = tid; i < 12288; i += 128) sWhh[i] = Whh[i];
    for (int i = tid; i < 192;   i += 128) sBhh[i] = bhh[i];
    for (int i = tid; i < 384;   i += 128) sWcd[i] = g_Wc_dec[i];
    for (int i = tid; i < 192;   i += 128) sBcd[i] = g_bc_dec[i];
    for (int i = tid; i < 4096;  i += 128) {
        int m = i >> 6, k = i & 63;
        sW1t[i] = oW1[k * 64 + m];
    }
    for (int i = tid; i < 768;   i += 128) {
        int m = i / 12, c = i % 12;
        sW2p[i] = (c < 10) ? oW2[m * 10 + c] : 0.f;
    }
    if (tid < 64) sB1[tid] = oB1[tid];
    if (tid < 16) sB2[tid] = (tid < 10) ? oB2[tid] : 0.f;
    __syncthreads();

    const int bn = blockIdx.x * 128 + tid;
    const int b  = bn / Nq;
    const int n  = bn % Nq;

    u64 h2[32];
    const u64* hf = reinterpret_cast<const u64*>(g_hfin) + (size_t)bn * 32;
    #pragma unroll
    for (int k = 0; k < 32; k++) { h2[k] = hf[k]; hsu[k * 128 + tid] = h2[k]; }

    // last-frame xy
    const float* xl = x + ((size_t)b * (Tq * Nq) + 4 * Nq + n) * Fq;
    float xy0 = xl[0];
    float xy1 = xl[1];

    for (int t = 0; t < TOq; t++) {
        #pragma unroll 1
        for (int jj = 0; jj < 32; jj++) {
            const int j = 2 * jj;
            const ulonglong2* wh0 = (const ulonglong2*)(sWhh + j * 64);
            const ulonglong2* wh1 = (const ulonglong2*)(sWhh + (j + 1) * 64);
            const ulonglong2* wh2 = (const ulonglong2*)(sWhh + (j + 64) * 64);
            const ulonglong2* wh3 = (const ulonglong2*)(sWhh + (j + 65) * 64);
            const ulonglong2* wh4 = (const ulonglong2*)(sWhh + (j + 128) * 64);
            const ulonglong2* wh5 = (const ulonglong2*)(sWhh + (j + 129) * 64);
            u64 r0 = 0, r1 = 0, z0 = 0, z1 = 0, n0 = 0, n1 = 0;
            #pragma unroll
            for (int k4 = 0; k4 < 16; k4++) {
                u64 ha = h2[2 * k4], hb = h2[2 * k4 + 1];
                ulonglong2 w;
                w = wh0[k4]; r0 = fma2(w.x, ha, r0); r0 = fma2(w.y, hb, r0);
                w = wh1[k4]; r1 = fma2(w.x, ha, r1); r1 = fma2(w.y, hb, r1);
                w = wh2[k4]; z0 = fma2(w.x, ha, z0); z0 = fma2(w.y, hb, z0);
                w = wh3[k4]; z1 = fma2(w.x, ha, z1); z1 = fma2(w.y, hb, z1);
                w = wh4[k4]; n0 = fma2(w.x, ha, n0); n0 = fma2(w.y, hb, n0);
                w = wh5[k4]; n1 = fma2(w.x, ha, n1); n1 = fma2(w.y, hb, n1);
            }
            float xr0 = sBcd[j]       + sWcd[j * 2] * xy0         + sWcd[j * 2 + 1] * xy1;
            float xr1 = sBcd[j + 1]   + sWcd[(j + 1) * 2] * xy0   + sWcd[(j + 1) * 2 + 1] * xy1;
            float xz0 = sBcd[j + 64]  + sWcd[(j + 64) * 2] * xy0  + sWcd[(j + 64) * 2 + 1] * xy1;
            float xz1 = sBcd[j + 65]  + sWcd[(j + 65) * 2] * xy0  + sWcd[(j + 65) * 2 + 1] * xy1;
            float xn0 = sBcd[j + 128] + sWcd[(j + 128) * 2] * xy0 + sWcd[(j + 128) * 2 + 1] * xy1;
            float xn1 = sBcd[j + 129] + sWcd[(j + 129) * 2] * xy0 + sWcd[(j + 129) * 2 + 1] * xy1;
            float R0 = sigmf(hadd(r0) + sBhh[j]      + xr0);
            float R1 = sigmf(hadd(r1) + sBhh[j + 1]  + xr1);
            float Z0 = sigmf(hadd(z0) + sBhh[j + 64] + xz0);
            float Z1 = sigmf(hadd(z1) + sBhh[j + 65] + xz1);
            float A0 = hadd(n0) + sBhh[j + 128];
            float A1 = hadd(n1) + sBhh[j + 129];
            float N0 = tanhf_(xn0 + R0 * A0);
            float N1 = tanhf_(xn1 + R1 * A1);
            float2 ho = unpk(hsu[jj * 128 + tid]);
            float hn0 = (1.f - Z0) * N0 + Z0 * ho.x;
            float hn1 = (1.f - Z1) * N1 + Z1 * ho.y;
            hsu[jj * 128 + tid] = pk(hn0, hn1);
        }
        #pragma unroll
        for (int k = 0; k < 32; k++) h2[k] = hsu[k * 128 + tid];

        // out MLP: o2 = relu(h @ W1 + b1) @ W2 + b2, packed
        u64 o2p[5];
        #pragma unroll
        for (int p = 0; p < 5; p++) o2p[p] = pk(sB2[2 * p], sB2[2 * p + 1]);
        #pragma unroll 2
        for (int m = 0; m < 64; m++) {
            const ulonglong2* w1 = (const ulonglong2*)(sW1t + m * 64);
            u64 acc = 0;
            #pragma unroll
            for (int k4 = 0; k4 < 16; k4++) {
                ulonglong2 wv = w1[k4];
                acc = fma2(wv.x, h2[2 * k4], acc);
                acc = fma2(wv.y, h2[2 * k4 + 1], acc);
            }
            float a = fmaxf(hadd(acc) + sB1[m], 0.f);
            u64 a2 = bc2(a);
            const u64* w2r = (const u64*)(sW2p + m * 12);
            #pragma unroll
            for (int p = 0; p < 5; p++) o2p[p] = fma2(a2, w2r[p], o2p[p]);
        }
        float o[10];
        #pragma unroll
        for (int p = 0; p < 5; p++) {
            float2 v = unpk(o2p[p]);
            o[2 * p] = v.x; o[2 * p + 1] = v.y;
        }

        // traj[b, m, n, t, c] = o[c*5 + m]
        size_t ob = (size_t)b * 300 + (size_t)n * 12 + t * 2;
        #pragma unroll
        for (int m = 0; m < 5; m++) {
            out[ob + m * 60 + 0] = o[m];
            out[ob + m * 60 + 1] = o[5 + m];
        }
        xy0 = o[0];
        xy1 = o[5];
    }
}

// ------------------------- launch -------------------------------------------
extern "C" void kernel_launch(void* const* d_in, const int* in_sizes, int n_in,
                              void* d_out, int out_size)
{
    const float* x        = (const float*)d_in[0];
    const float* embW     = (const float*)d_in[1];
    const float* embB     = (const float*)d_in[2];
    const float* gatW     = (const float*)d_in[3];
    const float* attSrc   = (const float*)d_in[4];
    const float* attDst   = (const float*)d_in[5];
    const float* gatB     = (const float*)d_in[6];
    const float* encWih   = (const float*)d_in[7];
    const float* encWhh   = (const float*)d_in[8];
    const float* encBih   = (const float*)d_in[9];
    const float* encBhh   = (const float*)d_in[10];
    const float* decWih   = (const float*)d_in[11];
    const float* decWhh   = (const float*)d_in[12];
    const float* decBih   = (const float*)d_in[13];
    const float* decBhh   = (const float*)d_in[14];
    const float* oW1      = (const float*)d_in[15];
    const float* oB1      = (const float*)d_in[16];
    const float* oW2      = (const float*)d_in[17];
    const float* oB2      = (const float*)d_in[18];
    const float* projW    = (const float*)d_in[19];
    const float* projB    = (const float*)d_in[20];
    const float* cW1      = (const float*)d_in[21];
    const float* cB1      = (const float*)d_in[22];
    const float* cW2      = (const float*)d_in[23];
    const float* cB2      = (const float*)d_in[24];
    float* out = (float*)d_out;

    cudaFuncSetAttribute(enc_kernel, cudaFuncAttributeMaxDynamicSharedMemorySize, ENC_SMEM_BYTES);
    cudaFuncSetAttribute(dec_kernel, cudaFuncAttributeMaxDynamicSharedMemorySize, DEC_SMEM_BYTES);

    prep_kernel<<<27, 128>>>(encWih, encBih, decWih, decBih,
                             embW, embB, projW, projB, gatW);

    enc_kernel<<<BNq / 128, 128, ENC_SMEM_BYTES>>>(x, encWhh, encBhh, attSrc, attDst);

    gat_kernel<<<BNq / 128, 128>>>(gatB, cW1, cB1, cW2, cB2, out);

    dec_kernel<<<BNq / 128, 128, DEC_SMEM_BYTES>>>(x, decWhh, decBhh,
                                                   oW1, oB1, oW2, oB2, out);
}

// round 7
// speedup vs baseline: 1.6919x; 1.1474x over previous
#include <cuda_runtime.h>
#include <cstdint>

// ---------------------------------------------------------------------------
// Model_78898549227585: embed -> GRU encoder (T=5) -> GATConv -> GRUCell
// decoder (T_OUT=6, autoregressive) + confidence head.
// B=32768, N=5, H=64, F=10, M=5.
// fp32x2-packed gate math, 2 nodes per thread (weight-load amortization + ILP).
// ---------------------------------------------------------------------------

#define DINL __device__ __forceinline__

typedef unsigned long long u64;

constexpr int Bq   = 32768;
constexpr int Tq   = 5;
constexpr int Nq   = 5;
constexpr int Fq   = 10;
constexpr int Hq   = 64;
constexpr int Gq   = 192;   // 3H
constexpr int Mq   = 5;
constexpr int TOq  = 6;
constexpr int BNq  = Bq * Nq;                       // 163840
constexpr long long TRAJ_ELEMS = (long long)Bq * Mq * Nq * TOq * 2;  // 9,830,400

// ------------------------- device scratch ---------------------------------
__device__ float g_Wc_enc[Gq * Fq];
__device__ float g_bc_enc[Gq];
__device__ float g_Wc_dec[Gq * 2];
__device__ float g_bc_dec[Gq];
__device__ float g_Wc_xl[Fq * Hq];
__device__ float g_b_xl[Hq];

__device__ __align__(16) float g_henc[(size_t)BNq * Hq];
__device__ __align__(16) float g_xl  [(size_t)BNq * Hq];
__device__ float g_as  [BNq];
__device__ float g_ad  [BNq];
__device__ int   g_mask[BNq];
__device__ __align__(16) float g_hfin[(size_t)BNq * Hq];

// ------------------------- packed helpers ----------------------------------
DINL u64 fma2(u64 a, u64 b, u64 c) {
    u64 d; asm("fma.rn.f32x2 %0,%1,%2,%3;" : "=l"(d) : "l"(a), "l"(b), "l"(c));
    return d;
}
DINL u64 add2(u64 a, u64 b) {
    u64 d; asm("add.rn.f32x2 %0,%1,%2;" : "=l"(d) : "l"(a), "l"(b));
    return d;
}
DINL float2 unpk(u64 v) {
    float2 f; asm("mov.b64 {%0,%1},%2;" : "=f"(f.x), "=f"(f.y) : "l"(v));
    return f;
}
DINL u64 pk(float lo, float hi) {
    u64 v; asm("mov.b64 %0,{%1,%2};" : "=l"(v) : "f"(lo), "f"(hi));
    return v;
}
DINL float hadd(u64 v) { float2 f = unpk(v); return f.x + f.y; }
DINL u64 bc2(float x)  { return pk(x, x); }

DINL float sigmf(float v)  { return __fdividef(1.f, 1.f + __expf(-v)); }
DINL float tanhf_(float v) { return 1.f - __fdividef(2.f, __expf(2.f * v) + 1.f); }

// ------------------------- prep: fold weights ------------------------------
__global__ void prep_kernel(const float* __restrict__ enc_Wih,
                            const float* __restrict__ enc_bih,
                            const float* __restrict__ dec_Wih,
                            const float* __restrict__ dec_bih,
                            const float* __restrict__ embW,
                            const float* __restrict__ embB,
                            const float* __restrict__ projW,
                            const float* __restrict__ projB,
                            const float* __restrict__ gatW)
{
    int t = blockIdx.x * blockDim.x + threadIdx.x;
    if (t < Gq * Fq) {
        int j = t / Fq, c = t % Fq;
        float s = 0.f;
        for (int k = 0; k < Hq; k++) s += enc_Wih[j * Hq + k] * embW[c * Hq + k];
        g_Wc_enc[j * Fq + c] = s;
    } else if (t < 1920 + 192) {
        int j = t - 1920;
        float s = enc_bih[j];
        for (int k = 0; k < Hq; k++) s += enc_Wih[j * Hq + k] * embB[k];
        g_bc_enc[j] = s;
    } else if (t < 2112 + 384) {
        int i = t - 2112;
        int j = i / 2, c = i % 2;
        float s = 0.f;
        for (int k = 0; k < Hq; k++) s += dec_Wih[j * Hq + k] * projW[c * Hq + k];
        g_Wc_dec[j * 2 + c] = s;
    } else if (t < 2496 + 192) {
        int j = t - 2496;
        float s = dec_bih[j];
        for (int k = 0; k < Hq; k++) s += dec_Wih[j * Hq + k] * projB[k];
        g_bc_dec[j] = s;
    } else if (t < 2688 + 640) {
        int i = t - 2688;
        int c = i / Hq, k2 = i % Hq;
        float s = 0.f;
        for (int k = 0; k < Hq; k++) s += embW[c * Hq + k] * gatW[k * Hq + k2];
        g_Wc_xl[c * Hq + k2] = s;
    } else if (t < 3328 + 64) {
        int k2 = t - 3328;
        float s = 0.f;
        for (int k = 0; k < Hq; k++) s += embB[k] * gatW[k * Hq + k2];
        g_b_xl[k2] = s;
    }
}

// ------------------------- encoder ------------------------------------------
// 256 threads, 2 nodes/thread (512 nodes/block).
// smem floats:
//  sWhh 12288 | sBhh 192 | sWc 2304 (stride 12) | sBc 192 | sWxl 640 |
//  sBxl 64 | sAs 64 | sAd 64 | hs 32*512 u64
constexpr int E_WHH = 0;
constexpr int E_BHH = 12288;
constexpr int E_WC  = 12480;
constexpr int E_BC  = 14784;
constexpr int E_WXL = 14976;
constexpr int E_BXL = 15616;
constexpr int E_AS  = 15680;
constexpr int E_AD  = 15744;
constexpr int E_HS  = 15808;
constexpr int ENC_SMEM_FLOATS = E_HS + 32 * 512 * 2;   // 48576
constexpr int ENC_SMEM_BYTES  = ENC_SMEM_FLOATS * 4;   // 194304

// encoder epilogue for one node: store h_enc, mask, xl, attention scalars
DINL void enc_epi(int bn, const u64* xq, const u64* h2,
                  const float* sWxl, const float* sBxl,
                  const float* sAs, const float* sAd)
{
    u64* ghe = reinterpret_cast<u64*>(g_henc) + (size_t)bn * 32;
    #pragma unroll
    for (int k = 0; k < 32; k++) ghe[k] = h2[k];

    float x10[10];
    #pragma unroll
    for (int c2 = 0; c2 < 5; c2++) {
        float2 v = unpk(xq[c2]);
        x10[2 * c2] = v.x; x10[2 * c2 + 1] = v.y;
    }
    float s6 = x10[0] + x10[1] + x10[2] + x10[3] + x10[4] + x10[5];
    g_mask[bn] = (s6 != 0.f) ? 1 : 0;

    u64 xb[10];
    #pragma unroll
    for (int c = 0; c < 10; c++) xb[c] = bc2(x10[c]);
    const u64* bxl2 = (const u64*)sBxl;
    const u64* asp  = (const u64*)sAs;
    const u64* adp  = (const u64*)sAd;
    u64* gxl = reinterpret_cast<u64*>(g_xl) + (size_t)bn * 32;
    u64 asum = 0, adsum = 0;
    #pragma unroll 2
    for (int k2 = 0; k2 < 32; k2++) {
        u64 acc = bxl2[k2];
        #pragma unroll
        for (int c = 0; c < 10; c++)
            acc = fma2(xb[c], *((const u64*)(sWxl + c * 64) + k2), acc);
        gxl[k2] = acc;
        asum  = fma2(acc, asp[k2], asum);
        adsum = fma2(acc, adp[k2], adsum);
    }
    g_as[bn] = hadd(asum);
    g_ad[bn] = hadd(adsum);
}

__global__ void __launch_bounds__(256) enc_kernel(
    const float* __restrict__ x,
    const float* __restrict__ Whh,
    const float* __restrict__ bhh,
    const float* __restrict__ asrc,
    const float* __restrict__ adst)
{
    extern __shared__ float sm[];
    float* sWhh = sm + E_WHH;
    float* sBhh = sm + E_BHH;
    float* sWc  = sm + E_WC;
    float* sBc  = sm + E_BC;
    float* sWxl = sm + E_WXL;
    float* sBxl = sm + E_BXL;
    float* sAs  = sm + E_AS;
    float* sAd  = sm + E_AD;
    u64*   hsu  = reinterpret_cast<u64*>(sm + E_HS);

    const int tid = threadIdx.x;
    for (int i = tid; i < 12288; i += 256) sWhh[i] = Whh[i];
    for (int i = tid; i < 2304;  i += 256) {
        int j = i / 12, c = i % 12;
        sWc[i] = (c < 10) ? g_Wc_enc[j * 10 + c] : 0.f;
    }
    if (tid < 192) { sBhh[tid] = bhh[tid]; sBc[tid] = g_bc_enc[tid]; }
    for (int i = tid; i < 640;   i += 256) sWxl[i] = g_Wc_xl[i];
    if (tid < 64) { sBxl[tid] = g_b_xl[tid]; sAs[tid] = asrc[tid]; sAd[tid] = adst[tid]; }
    __syncthreads();

    const int bnA = blockIdx.x * 512 + tid;
    const int bnB = bnA + 256;
    const float* xpA = x + ((size_t)(bnA / Nq) * (Tq * Nq) + (bnA % Nq)) * Fq;
    const float* xpB = x + ((size_t)(bnB / Nq) * (Tq * Nq) + (bnB % Nq)) * Fq;

    u64 h2a[32], h2b[32];
    #pragma unroll
    for (int k = 0; k < 32; k++) {
        h2a[k] = 0ULL; h2b[k] = 0ULL;
        hsu[k * 512 + tid] = 0ULL; hsu[k * 512 + tid + 256] = 0ULL;
    }

    u64 xqA[5], xqB[5];

    for (int t = 0; t < Tq; t++) {
        {
            const float2* a2 = reinterpret_cast<const float2*>(xpA + (size_t)t * (Nq * Fq));
            const float2* b2 = reinterpret_cast<const float2*>(xpB + (size_t)t * (Nq * Fq));
            #pragma unroll
            for (int c2 = 0; c2 < 5; c2++) {
                float2 va = a2[c2]; xqA[c2] = pk(va.x, va.y);
                float2 vb = b2[c2]; xqB[c2] = pk(vb.x, vb.y);
            }
        }

        #pragma unroll 1
        for (int jj = 0; jj < 32; jj++) {
            const int j = 2 * jj;
            const ulonglong2* wh0 = (const ulonglong2*)(sWhh + j * 64);
            const ulonglong2* wh1 = (const ulonglong2*)(sWhh + (j + 1) * 64);
            const ulonglong2* wh2 = (const ulonglong2*)(sWhh + (j + 64) * 64);
            const ulonglong2* wh3 = (const ulonglong2*)(sWhh + (j + 65) * 64);
            const ulonglong2* wh4 = (const ulonglong2*)(sWhh + (j + 128) * 64);
            const ulonglong2* wh5 = (const ulonglong2*)(sWhh + (j + 129) * 64);
            u64 rA0 = 0, rA1 = 0, zA0 = 0, zA1 = 0, nA0 = 0, nA1 = 0;
            u64 rB0 = 0, rB1 = 0, zB0 = 0, zB1 = 0, nB0 = 0, nB1 = 0;
            #pragma unroll
            for (int k4 = 0; k4 < 16; k4++) {
                u64 haA = h2a[2 * k4], hbA = h2a[2 * k4 + 1];
                u64 haB = h2b[2 * k4], hbB = h2b[2 * k4 + 1];
                ulonglong2 w;
                w = wh0[k4];
                rA0 = fma2(w.x, haA, rA0); rA0 = fma2(w.y, hbA, rA0);
                rB0 = fma2(w.x, haB, rB0); rB0 = fma2(w.y, hbB, rB0);
                w = wh1[k4];
                rA1 = fma2(w.x, haA, rA1); rA1 = fma2(w.y, hbA, rA1);
                rB1 = fma2(w.x, haB, rB1); rB1 = fma2(w.y, hbB, rB1);
                w = wh2[k4];
                zA0 = fma2(w.x, haA, zA0); zA0 = fma2(w.y, hbA, zA0);
                zB0 = fma2(w.x, haB, zB0); zB0 = fma2(w.y, hbB, zB0);
                w = wh3[k4];
                zA1 = fma2(w.x, haA, zA1); zA1 = fma2(w.y, hbA, zA1);
                zB1 = fma2(w.x, haB, zB1); zB1 = fma2(w.y, hbB, zB1);
                w = wh4[k4];
                nA0 = fma2(w.x, haA, nA0); nA0 = fma2(w.y, hbA, nA0);
                nB0 = fma2(w.x, haB, nB0); nB0 = fma2(w.y, hbB, nB0);
                w = wh5[k4];
                nA1 = fma2(w.x, haA, nA1); nA1 = fma2(w.y, hbA, nA1);
                nB1 = fma2(w.x, haB, nB1); nB1 = fma2(w.y, hbB, nB1);
            }
            // x-path: fold r,z into accumulators; n kept separate per node
            const u64* cx0 = (const u64*)(sWc + j * 12);
            const u64* cx1 = (const u64*)(sWc + (j + 1) * 12);
            const u64* cx2 = (const u64*)(sWc + (j + 64) * 12);
            const u64* cx3 = (const u64*)(sWc + (j + 65) * 12);
            const u64* cx4 = (const u64*)(sWc + (j + 128) * 12);
            const u64* cx5 = (const u64*)(sWc + (j + 129) * 12);
            u64 xnA0 = 0, xnA1 = 0, xnB0 = 0, xnB1 = 0;
            #pragma unroll
            for (int c2 = 0; c2 < 5; c2++) {
                u64 xa = xqA[c2], xb = xqB[c2];
                u64 c0 = cx0[c2], c1 = cx1[c2], c2v = cx2[c2],
                    c3 = cx3[c2], c4 = cx4[c2], c5 = cx5[c2];
                rA0  = fma2(c0, xa, rA0);   rB0  = fma2(c0, xb, rB0);
                rA1  = fma2(c1, xa, rA1);   rB1  = fma2(c1, xb, rB1);
                zA0  = fma2(c2v, xa, zA0);  zB0  = fma2(c2v, xb, zB0);
                zA1  = fma2(c3, xa, zA1);   zB1  = fma2(c3, xb, zB1);
                xnA0 = fma2(c4, xa, xnA0);  xnB0 = fma2(c4, xb, xnB0);
                xnA1 = fma2(c5, xa, xnA1);  xnB1 = fma2(c5, xb, xnB1);
            }
            float b0 = sBhh[j] + sBc[j], b1 = sBhh[j + 1] + sBc[j + 1];
            float b2 = sBhh[j + 64] + sBc[j + 64], b3 = sBhh[j + 65] + sBc[j + 65];
            float bn0 = sBhh[j + 128], bn1 = sBhh[j + 129];
            float bx0 = sBc[j + 128],  bx1 = sBc[j + 129];
            // node A
            {
                float R0 = sigmf(hadd(rA0) + b0);
                float R1 = sigmf(hadd(rA1) + b1);
                float Z0 = sigmf(hadd(zA0) + b2);
                float Z1 = sigmf(hadd(zA1) + b3);
                float N0 = tanhf_(hadd(xnA0) + bx0 + R0 * (hadd(nA0) + bn0));
                float N1 = tanhf_(hadd(xnA1) + bx1 + R1 * (hadd(nA1) + bn1));
                float2 ho = unpk(hsu[jj * 512 + tid]);
                hsu[jj * 512 + tid] = pk((1.f - Z0) * N0 + Z0 * ho.x,
                                         (1.f - Z1) * N1 + Z1 * ho.y);
            }
            // node B
            {
                float R0 = sigmf(hadd(rB0) + b0);
                float R1 = sigmf(hadd(rB1) + b1);
                float Z0 = sigmf(hadd(zB0) + b2);
                float Z1 = sigmf(hadd(zB1) + b3);
                float N0 = tanhf_(hadd(xnB0) + bx0 + R0 * (hadd(nB0) + bn0));
                float N1 = tanhf_(hadd(xnB1) + bx1 + R1 * (hadd(nB1) + bn1));
                float2 ho = unpk(hsu[jj * 512 + tid + 256]);
                hsu[jj * 512 + tid + 256] = pk((1.f - Z0) * N0 + Z0 * ho.x,
                                               (1.f - Z1) * N1 + Z1 * ho.y);
            }
        }
        #pragma unroll
        for (int k = 0; k < 32; k++) {
            h2a[k] = hsu[k * 512 + tid];
            h2b[k] = hsu[k * 512 + tid + 256];
        }
    }

    enc_epi(bnA, xqA, h2a, sWxl, sBxl, sAs, sAd);
    enc_epi(bnB, xqB, h2b, sWxl, sBxl, sAs, sAd);
}

// ------------------------- GAT + conf ---------------------------------------
__global__ void __launch_bounds__(128) gat_kernel(
    const float* __restrict__ gat_b,
    const float* __restrict__ cW1,
    const float* __restrict__ cB1,
    const float* __restrict__ cW2,
    const float* __restrict__ cB2,
    float* __restrict__ out)
{
    __shared__ __align__(16) float sW1t[4096];   // [m][k]
    __shared__ __align__(16) float sB1[64];
    __shared__ __align__(16) float sW2[512];     // [m][p] padded stride 8
    __shared__ __align__(16) float sB2[8];
    __shared__ __align__(16) float sGb[64];

    const int tid = threadIdx.x;
    for (int i = tid; i < 4096; i += 128) {
        int m = i >> 6, k = i & 63;
        sW1t[i] = cW1[k * 64 + m];
    }
    for (int i = tid; i < 512; i += 128) {
        int m = i >> 3, p = i & 7;
        sW2[i] = (p < 5) ? cW2[m * 5 + p] : 0.f;
    }
    if (tid < 64) { sB1[tid] = cB1[tid]; sGb[tid] = gat_b[tid]; }
    if (tid < 8)  sB2[tid] = (tid < 5) ? cB2[tid] : 0.f;
    __syncthreads();

    const int bn = blockIdx.x * 128 + tid;
    const int b  = bn / Nq;
    const int n  = bn % Nq;
    const int base = b * Nq;

    float ad_i = g_ad[bn];
    int   mi   = g_mask[bn];

    float w[5];
    float amax = -1e30f;
    #pragma unroll
    for (int j = 0; j < 5; j++) {
        int src = base + j;
        float a = g_as[src] + ad_i;
        a = a > 0.f ? a : 0.2f * a;
        bool valid = (j == n) ? true : (mi && g_mask[src]);
        w[j] = valid ? a : -1e30f;
        amax = fmaxf(amax, w[j]);
    }
    float denom = 0.f;
    #pragma unroll
    for (int j = 0; j < 5; j++) {
        float e = __expf(w[j] - amax);
        w[j] = e;
        denom += e;
    }
    float inv = __fdividef(1.f, denom);
    #pragma unroll
    for (int j = 0; j < 5; j++) w[j] *= inv;

    u64 acc2[32];
    #pragma unroll
    for (int k = 0; k < 32; k++) acc2[k] = 0ULL;
    #pragma unroll
    for (int j = 0; j < 5; j++) {
        const u64* xr = reinterpret_cast<const u64*>(g_xl) + (size_t)(base + j) * 32;
        u64 wj = bc2(w[j]);
        #pragma unroll
        for (int k = 0; k < 32; k++) acc2[k] = fma2(wj, xr[k], acc2[k]);
    }

    u64 hfp[32];
    const u64* he = reinterpret_cast<const u64*>(g_henc) + (size_t)bn * 32;
    const u64* gb = (const u64*)sGb;
    u64* hfo = reinterpret_cast<u64*>(g_hfin) + (size_t)bn * 32;
    #pragma unroll
    for (int k = 0; k < 32; k++) {
        u64 r = add2(add2(he[k], acc2[k]), gb[k]);
        hfp[k] = r;
        hfo[k] = r;
    }

    u64 o2p[3];
    o2p[0] = pk(sB2[0], sB2[1]);
    o2p[1] = pk(sB2[2], sB2[3]);
    o2p[2] = pk(sB2[4], 0.f);
    #pragma unroll 2
    for (int m = 0; m < 64; m++) {
        const ulonglong2* w1 = (const ulonglong2*)(sW1t + m * 64);
        u64 acc = 0;
        #pragma unroll
        for (int k4 = 0; k4 < 16; k4++) {
            ulonglong2 wv = w1[k4];
            acc = fma2(wv.x, hfp[2 * k4], acc);
            acc = fma2(wv.y, hfp[2 * k4 + 1], acc);
        }
        float t = fmaxf(hadd(acc) + sB1[m], 0.f);
        u64 t2 = bc2(t);
        const u64* w2r = (const u64*)(sW2 + m * 8);
        o2p[0] = fma2(t2, w2r[0], o2p[0]);
        o2p[1] = fma2(t2, w2r[1], o2p[1]);
        o2p[2] = fma2(t2, w2r[2], o2p[2]);
    }
    float o[5];
    { float2 a = unpk(o2p[0]); o[0] = a.x; o[1] = a.y; }
    { float2 a = unpk(o2p[1]); o[2] = a.x; o[3] = a.y; }
    { float2 a = unpk(o2p[2]); o[4] = a.x; }
    float mx = o[0];
    #pragma unroll
    for (int p = 1; p < 5; p++) mx = fmaxf(mx, o[p]);
    float s = 0.f;
    #pragma unroll
    for (int p = 0; p < 5; p++) { o[p] = __expf(o[p] - mx); s += o[p]; }
    float invs = __fdividef(1.f, s);

    float* conf = out + TRAJ_ELEMS;
    #pragma unroll
    for (int p = 0; p < 5; p++)
        conf[(size_t)b * 25 + p * 5 + n] = o[p] * invs;
}

// ------------------------- decoder ------------------------------------------
// 256 threads, 2 nodes/thread.
// smem floats:
//  sWhh 12288 | sBhh 192 | sWcd 384 | sBcd 192 | sW1t 4096 | sB1 64 |
//  sW2p 768 (stride 12) | sB2 16 | hs 32*512 u64
constexpr int D_WHH = 0;
constexpr int D_BHH = 12288;
constexpr int D_WCD = 12480;
constexpr int D_BCD = 12864;
constexpr int D_W1T = 13056;
constexpr int D_B1  = 17152;
constexpr int D_W2  = 17216;
constexpr int D_B2  = 17984;
constexpr int D_HS  = 18000;
constexpr int DEC_SMEM_FLOATS = D_HS + 32 * 512 * 2;   // 50768
constexpr int DEC_SMEM_BYTES  = DEC_SMEM_FLOATS * 4;   // 203072

__global__ void __launch_bounds__(256) dec_kernel(
    const float* __restrict__ x,
    const float* __restrict__ Whh,
    const float* __restrict__ bhh,
    const float* __restrict__ oW1,
    const float* __restrict__ oB1,
    const float* __restrict__ oW2,
    const float* __restrict__ oB2,
    float* __restrict__ out)
{
    extern __shared__ float sm[];
    float* sWhh = sm + D_WHH;
    float* sBhh = sm + D_BHH;
    float* sWcd = sm + D_WCD;
    float* sBcd = sm + D_BCD;
    float* sW1t = sm + D_W1T;
    float* sB1  = sm + D_B1;
    float* sW2p = sm + D_W2;
    float* sB2  = sm + D_B2;
    u64*   hsu  = reinterpret_cast<u64*>(sm + D_HS);

    const int tid = threadIdx.x;
    for (int i = tid; i < 12288; i += 256) sWhh[i] = Whh[i];
    if (tid < 192) { sBhh[tid] = bhh[tid]; sBcd[tid] = g_bc_dec[tid]; }
    for (int i = tid; i < 384;   i += 256) sWcd[i] = g_Wc_dec[i];
    for (int i = tid; i < 4096;  i += 256) {
        int m = i >> 6, k = i & 63;
        sW1t[i] = oW1[k * 64 + m];
    }
    for (int i = tid; i < 768;   i += 256) {
        int m = i / 12, c = i % 12;
        sW2p[i] = (c < 10) ? oW2[m * 10 + c] : 0.f;
    }
    if (tid < 64) sB1[tid] = oB1[tid];
    if (tid < 16) sB2[tid] = (tid < 10) ? oB2[tid] : 0.f;
    __syncthreads();

    const int bnA = blockIdx.x * 512 + tid;
    const int bnB = bnA + 256;
    const int bA = bnA / Nq, nA = bnA % Nq;
    const int bB = bnB / Nq, nB = bnB % Nq;

    u64 h2a[32], h2b[32];
    {
        const u64* hfA = reinterpret_cast<const u64*>(g_hfin) + (size_t)bnA * 32;
        const u64* hfB = reinterpret_cast<const u64*>(g_hfin) + (size_t)bnB * 32;
        #pragma unroll
        for (int k = 0; k < 32; k++) {
            h2a[k] = hfA[k]; hsu[k * 512 + tid] = h2a[k];
            h2b[k] = hfB[k]; hsu[k * 512 + tid + 256] = h2b[k];
        }
    }

    const float* xlA = x + ((size_t)bA * (Tq * Nq) + 4 * Nq + nA) * Fq;
    const float* xlB = x + ((size_t)bB * (Tq * Nq) + 4 * Nq + nB) * Fq;
    float xyA0 = xlA[0], xyA1 = xlA[1];
    float xyB0 = xlB[0], xyB1 = xlB[1];

    for (int t = 0; t < TOq; t++) {
        #pragma unroll 1
        for (int jj = 0; jj < 32; jj++) {
            const int j = 2 * jj;
            const ulonglong2* wh0 = (const ulonglong2*)(sWhh + j * 64);
            const ulonglong2* wh1 = (const ulonglong2*)(sWhh + (j + 1) * 64);
            const ulonglong2* wh2 = (const ulonglong2*)(sWhh + (j + 64) * 64);
            const ulonglong2* wh3 = (const ulonglong2*)(sWhh + (j + 65) * 64);
            const ulonglong2* wh4 = (const ulonglong2*)(sWhh + (j + 128) * 64);
            const ulonglong2* wh5 = (const ulonglong2*)(sWhh + (j + 129) * 64);
            u64 rA0 = 0, rA1 = 0, zA0 = 0, zA1 = 0, nA0 = 0, nA1 = 0;
            u64 rB0 = 0, rB1 = 0, zB0 = 0, zB1 = 0, nB0 = 0, nB1 = 0;
            #pragma unroll
            for (int k4 = 0; k4 < 16; k4++) {
                u64 haA = h2a[2 * k4], hbA = h2a[2 * k4 + 1];
                u64 haB = h2b[2 * k4], hbB = h2b[2 * k4 + 1];
                ulonglong2 w;
                w = wh0[k4];
                rA0 = fma2(w.x, haA, rA0); rA0 = fma2(w.y, hbA, rA0);
                rB0 = fma2(w.x, haB, rB0); rB0 = fma2(w.y, hbB, rB0);
                w = wh1[k4];
                rA1 = fma2(w.x, haA, rA1); rA1 = fma2(w.y, hbA, rA1);
                rB1 = fma2(w.x, haB, rB1); rB1 = fma2(w.y, hbB, rB1);
                w = wh2[k4];
                zA0 = fma2(w.x, haA, zA0); zA0 = fma2(w.y, hbA, zA0);
                zB0 = fma2(w.x, haB, zB0); zB0 = fma2(w.y, hbB, zB0);
                w = wh3[k4];
                zA1 = fma2(w.x, haA, zA1); zA1 = fma2(w.y, hbA, zA1);
                zB1 = fma2(w.x, haB, zB1); zB1 = fma2(w.y, hbB, zB1);
                w = wh4[k4];
                nA0 = fma2(w.x, haA, nA0); nA0 = fma2(w.y, hbA, nA0);
                nB0 = fma2(w.x, haB, nB0); nB0 = fma2(w.y, hbB, nB0);
                w = wh5[k4];
                nA1 = fma2(w.x, haA, nA1); nA1 = fma2(w.y, hbA, nA1);
                nB1 = fma2(w.x, haB, nB1); nB1 = fma2(w.y, hbB, nB1);
            }
            float w00 = sWcd[j * 2],         w01 = sWcd[j * 2 + 1];
            float w10 = sWcd[(j + 1) * 2],   w11 = sWcd[(j + 1) * 2 + 1];
            float w20 = sWcd[(j + 64) * 2],  w21 = sWcd[(j + 64) * 2 + 1];
            float w30 = sWcd[(j + 65) * 2],  w31 = sWcd[(j + 65) * 2 + 1];
            float w40 = sWcd[(j + 128) * 2], w41 = sWcd[(j + 128) * 2 + 1];
            float w50 = sWcd[(j + 129) * 2], w51 = sWcd[(j + 129) * 2 + 1];
            float br0 = sBcd[j] + sBhh[j],           br1 = sBcd[j + 1] + sBhh[j + 1];
            float bz0 = sBcd[j + 64] + sBhh[j + 64], bz1 = sBcd[j + 65] + sBhh[j + 65];
            float bxn0 = sBcd[j + 128], bxn1 = sBcd[j + 129];
            float bn0 = sBhh[j + 128],  bn1 = sBhh[j + 129];
            // node A
            {
                float R0 = sigmf(hadd(rA0) + br0 + w00 * xyA0 + w01 * xyA1);
                float R1 = sigmf(hadd(rA1) + br1 + w10 * xyA0 + w11 * xyA1);
                float Z0 = sigmf(hadd(zA0) + bz0 + w20 * xyA0 + w21 * xyA1);
                float Z1 = sigmf(hadd(zA1) + bz1 + w30 * xyA0 + w31 * xyA1);
                float N0 = tanhf_(bxn0 + w40 * xyA0 + w41 * xyA1 + R0 * (hadd(nA0) + bn0));
                float N1 = tanhf_(bxn1 + w50 * xyA0 + w51 * xyA1 + R1 * (hadd(nA1) + bn1));
                float2 ho = unpk(hsu[jj * 512 + tid]);
                hsu[jj * 512 + tid] = pk((1.f - Z0) * N0 + Z0 * ho.x,
                                         (1.f - Z1) * N1 + Z1 * ho.y);
            }
            // node B
            {
                float R0 = sigmf(hadd(rB0) + br0 + w00 * xyB0 + w01 * xyB1);
                float R1 = sigmf(hadd(rB1) + br1 + w10 * xyB0 + w11 * xyB1);
                float Z0 = sigmf(hadd(zB0) + bz0 + w20 * xyB0 + w21 * xyB1);
                float Z1 = sigmf(hadd(zB1) + bz1 + w30 * xyB0 + w31 * xyB1);
                float N0 = tanhf_(bxn0 + w40 * xyB0 + w41 * xyB1 + R0 * (hadd(nB0) + bn0));
                float N1 = tanhf_(bxn1 + w50 * xyB0 + w51 * xyB1 + R1 * (hadd(nB1) + bn1));
                float2 ho = unpk(hsu[jj * 512 + tid + 256]);
                hsu[jj * 512 + tid + 256] = pk((1.f - Z0) * N0 + Z0 * ho.x,
                                               (1.f - Z1) * N1 + Z1 * ho.y);
            }
        }
        #pragma unroll
        for (int k = 0; k < 32; k++) {
            h2a[k] = hsu[k * 512 + tid];
            h2b[k] = hsu[k * 512 + tid + 256];
        }

        // out MLP for both nodes, shared weight loads
        u64 oA[5], oB[5];
        #pragma unroll
        for (int p = 0; p < 5; p++) {
            oA[p] = pk(sB2[2 * p], sB2[2 * p + 1]);
            oB[p] = oA[p];
        }
        #pragma unroll 2
        for (int m = 0; m < 64; m++) {
            const ulonglong2* w1 = (const ulonglong2*)(sW1t + m * 64);
            u64 accA = 0, accB = 0;
            #pragma unroll
            for (int k4 = 0; k4 < 16; k4++) {
                ulonglong2 wv = w1[k4];
                accA = fma2(wv.x, h2a[2 * k4], accA);
                accA = fma2(wv.y, h2a[2 * k4 + 1], accA);
                accB = fma2(wv.x, h2b[2 * k4], accB);
                accB = fma2(wv.y, h2b[2 * k4 + 1], accB);
            }
            float aA = fmaxf(hadd(accA) + sB1[m], 0.f);
            float aB = fmaxf(hadd(accB) + sB1[m], 0.f);
            u64 aA2 = bc2(aA), aB2 = bc2(aB);
            const u64* w2r = (const u64*)(sW2p + m * 12);
            #pragma unroll
            for (int p = 0; p < 5; p++) {
                u64 wv = w2r[p];
                oA[p] = fma2(aA2, wv, oA[p]);
                oB[p] = fma2(aB2, wv, oB[p]);
            }
        }

        float foA[10], foB[10];
        #pragma unroll
        for (int p = 0; p < 5; p++) {
            float2 va = unpk(oA[p]); foA[2 * p] = va.x; foA[2 * p + 1] = va.y;
            float2 vb = unpk(oB[p]); foB[2 * p] = vb.x; foB[2 * p + 1] = vb.y;
        }

        // traj[b, m, n, t, c] = o[c*5 + m]
        size_t obA = (size_t)bA * 300 + (size_t)nA * 12 + t * 2;
        size_t obB = (size_t)bB * 300 + (size_t)nB * 12 + t * 2;
        #pragma unroll
        for (int m = 0; m < 5; m++) {
            out[obA + m * 60 + 0] = foA[m];
            out[obA + m * 60 + 1] = foA[5 + m];
            out[obB + m * 60 + 0] = foB[m];
            out[obB + m * 60 + 1] = foB[5 + m];
        }
        xyA0 = foA[0]; xyA1 = foA[5];
        xyB0 = foB[0]; xyB1 = foB[5];
    }
}

// ------------------------- launch -------------------------------------------
extern "C" void kernel_launch(void* const* d_in, const int* in_sizes, int n_in,
                              void* d_out, int out_size)
{
    const float* x        = (const float*)d_in[0];
    const float* embW     = (const float*)d_in[1];
    const float* embB     = (const float*)d_in[2];
    const float* gatW     = (const float*)d_in[3];
    const float* attSrc   = (const float*)d_in[4];
    const float* attDst   = (const float*)d_in[5];
    const float* gatB     = (const float*)d_in[6];
    const float* encWih   = (const float*)d_in[7];
    const float* encWhh   = (const float*)d_in[8];
    const float* encBih   = (const float*)d_in[9];
    const float* encBhh   = (const float*)d_in[10];
    const float* decWih   = (const float*)d_in[11];
    const float* decWhh   = (const float*)d_in[12];
    const float* decBih   = (const float*)d_in[13];
    const float* decBhh   = (const float*)d_in[14];
    const float* oW1      = (const float*)d_in[15];
    const float* oB1      = (const float*)d_in[16];
    const float* oW2      = (const float*)d_in[17];
    const float* oB2      = (const float*)d_in[18];
    const float* projW    = (const float*)d_in[19];
    const float* projB    = (const float*)d_in[20];
    const float* cW1      = (const float*)d_in[21];
    const float* cB1      = (const float*)d_in[22];
    const float* cW2      = (const float*)d_in[23];
    const float* cB2      = (const float*)d_in[24];
    float* out = (float*)d_out;

    cudaFuncSetAttribute(enc_kernel, cudaFuncAttributeMaxDynamicSharedMemorySize, ENC_SMEM_BYTES);
    cudaFuncSetAttribute(dec_kernel, cudaFuncAttributeMaxDynamicSharedMemorySize, DEC_SMEM_BYTES);

    prep_kernel<<<27, 128>>>(encWih, encBih, decWih, decBih,
                             embW, embB, projW, projB, gatW);

    enc_kernel<<<BNq / 512, 256, ENC_SMEM_BYTES>>>(x, encWhh, encBhh, attSrc, attDst);

    gat_kernel<<<BNq / 128, 128>>>(gatB, cW1, cB1, cW2, cB2, out);

    dec_kernel<<<BNq / 512, 256, DEC_SMEM_BYTES>>>(x, decWhh, decBhh,
                                                   oW1, oB1, oW2, oB2, out);
}

// round 12
// speedup vs baseline: 1.7016x; 1.0058x over previous
#include <cuda_runtime.h>
#include <cstdint>

// ---------------------------------------------------------------------------
// Model_78898549227585: embed -> GRU encoder (T=5) -> GATConv -> GRUCell
// decoder (T_OUT=6, autoregressive) + confidence head.
// B=32768, T=5, N=5, H=64, F=10, M=5.
// fp32x2-packed gate math, 2 nodes/thread, persistent blocks (grid = 2*148)
// looping over 512-node tiles to kill the wave-quantization tail.
// ---------------------------------------------------------------------------

#define DINL __device__ __forceinline__

typedef unsigned long long u64;

constexpr int Bq   = 32768;
constexpr int Tq   = 5;
constexpr int Nq   = 5;
constexpr int Fq   = 10;
constexpr int Hq   = 64;
constexpr int Gq   = 192;   // 3H
constexpr int Mq   = 5;
constexpr int TOq  = 6;
constexpr int BNq  = Bq * Nq;                       // 163840
constexpr int TILES = BNq / 512;                    // 320
constexpr int GRID  = 296;                          // 2 * 148 SMs
constexpr long long TRAJ_ELEMS = (long long)Bq * Mq * Nq * TOq * 2;  // 9,830,400

// ------------------------- device scratch ---------------------------------
__device__ float g_Wc_enc[Gq * Fq];
__device__ float g_bc_enc[Gq];
__device__ float g_Wc_dec[Gq * 2];
__device__ float g_bc_dec[Gq];
__device__ float g_Wc_xl[Fq * Hq];
__device__ float g_b_xl[Hq];

__device__ __align__(16) float g_henc[(size_t)BNq * Hq];
__device__ __align__(16) float g_xl  [(size_t)BNq * Hq];
__device__ float g_as  [BNq];
__device__ float g_ad  [BNq];
__device__ int   g_mask[BNq];
__device__ __align__(16) float g_hfin[(size_t)BNq * Hq];

// ------------------------- packed helpers ----------------------------------
DINL u64 fma2(u64 a, u64 b, u64 c) {
    u64 d; asm("fma.rn.f32x2 %0,%1,%2,%3;" : "=l"(d) : "l"(a), "l"(b), "l"(c));
    return d;
}
DINL u64 add2(u64 a, u64 b) {
    u64 d; asm("add.rn.f32x2 %0,%1,%2;" : "=l"(d) : "l"(a), "l"(b));
    return d;
}
DINL float2 unpk(u64 v) {
    float2 f; asm("mov.b64 {%0,%1},%2;" : "=f"(f.x), "=f"(f.y) : "l"(v));
    return f;
}
DINL u64 pk(float lo, float hi) {
    u64 v; asm("mov.b64 %0,{%1,%2};" : "=l"(v) : "f"(lo), "f"(hi));
    return v;
}
DINL float hadd(u64 v) { float2 f = unpk(v); return f.x + f.y; }
DINL u64 bc2(float x)  { return pk(x, x); }

DINL float sigmf(float v)  { return __fdividef(1.f, 1.f + __expf(-v)); }
DINL float tanhf_(float v) { return 1.f - __fdividef(2.f, __expf(2.f * v) + 1.f); }

// ------------------------- prep: fold weights ------------------------------
__global__ void prep_kernel(const float* __restrict__ enc_Wih,
                            const float* __restrict__ enc_bih,
                            const float* __restrict__ dec_Wih,
                            const float* __restrict__ dec_bih,
                            const float* __restrict__ embW,
                            const float* __restrict__ embB,
                            const float* __restrict__ projW,
                            const float* __restrict__ projB,
                            const float* __restrict__ gatW)
{
    int t = blockIdx.x * blockDim.x + threadIdx.x;
    if (t < Gq * Fq) {
        int j = t / Fq, c = t % Fq;
        float s = 0.f;
        for (int k = 0; k < Hq; k++) s += enc_Wih[j * Hq + k] * embW[c * Hq + k];
        g_Wc_enc[j * Fq + c] = s;
    } else if (t < 1920 + 192) {
        int j = t - 1920;
        float s = enc_bih[j];
        for (int k = 0; k < Hq; k++) s += enc_Wih[j * Hq + k] * embB[k];
        g_bc_enc[j] = s;
    } else if (t < 2112 + 384) {
        int i = t - 2112;
        int j = i / 2, c = i % 2;
        float s = 0.f;
        for (int k = 0; k < Hq; k++) s += dec_Wih[j * Hq + k] * projW[c * Hq + k];
        g_Wc_dec[j * 2 + c] = s;
    } else if (t < 2496 + 192) {
        int j = t - 2496;
        float s = dec_bih[j];
        for (int k = 0; k < Hq; k++) s += dec_Wih[j * Hq + k] * projB[k];
        g_bc_dec[j] = s;
    } else if (t < 2688 + 640) {
        int i = t - 2688;
        int c = i / Hq, k2 = i % Hq;
        float s = 0.f;
        for (int k = 0; k < Hq; k++) s += embW[c * Hq + k] * gatW[k * Hq + k2];
        g_Wc_xl[c * Hq + k2] = s;
    } else if (t < 3328 + 64) {
        int k2 = t - 3328;
        float s = 0.f;
        for (int k = 0; k < Hq; k++) s += embB[k] * gatW[k * Hq + k2];
        g_b_xl[k2] = s;
    }
}

// ------------------------- encoder ------------------------------------------
// 256 threads, 2 nodes/thread, persistent over tiles of 512 nodes.
// smem floats:
//  sWhh 12288 | sBhh 192 | sWc 2304 (stride 12) | sBc 192 | sWxl 640 |
//  sBxl 64 | sAs 64 | sAd 64 | hs 32*512 u64
constexpr int E_WHH = 0;
constexpr int E_BHH = 12288;
constexpr int E_WC  = 12480;
constexpr int E_BC  = 14784;
constexpr int E_WXL = 14976;
constexpr int E_BXL = 15616;
constexpr int E_AS  = 15680;
constexpr int E_AD  = 15744;
constexpr int E_HS  = 15808;
constexpr int ENC_SMEM_FLOATS = E_HS + 32 * 512 * 2;   // 48576
constexpr int ENC_SMEM_BYTES  = ENC_SMEM_FLOATS * 4;   // 194304

// encoder epilogue for one node
DINL void enc_epi(int bn, const u64* xq, const u64* h2,
                  const float* sWxl, const float* sBxl,
                  const float* sAs, const float* sAd)
{
    u64* ghe = reinterpret_cast<u64*>(g_henc) + (size_t)bn * 32;
    #pragma unroll
    for (int k = 0; k < 32; k++) ghe[k] = h2[k];

    float x10[10];
    #pragma unroll
    for (int c2 = 0; c2 < 5; c2++) {
        float2 v = unpk(xq[c2]);
        x10[2 * c2] = v.x; x10[2 * c2 + 1] = v.y;
    }
    float s6 = x10[0] + x10[1] + x10[2] + x10[3] + x10[4] + x10[5];
    g_mask[bn] = (s6 != 0.f) ? 1 : 0;

    u64 xb[10];
    #pragma unroll
    for (int c = 0; c < 10; c++) xb[c] = bc2(x10[c]);
    const u64* bxl2 = (const u64*)sBxl;
    const u64* asp  = (const u64*)sAs;
    const u64* adp  = (const u64*)sAd;
    u64* gxl = reinterpret_cast<u64*>(g_xl) + (size_t)bn * 32;
    u64 asum = 0, adsum = 0;
    #pragma unroll 2
    for (int k2 = 0; k2 < 32; k2++) {
        u64 acc = bxl2[k2];
        #pragma unroll
        for (int c = 0; c < 10; c++)
            acc = fma2(xb[c], *((const u64*)(sWxl + c * 64) + k2), acc);
        gxl[k2] = acc;
        asum  = fma2(acc, asp[k2], asum);
        adsum = fma2(acc, adp[k2], adsum);
    }
    g_as[bn] = hadd(asum);
    g_ad[bn] = hadd(adsum);
}

__global__ void __launch_bounds__(256) enc_kernel(
    const float* __restrict__ x,
    const float* __restrict__ Whh,
    const float* __restrict__ bhh,
    const float* __restrict__ asrc,
    const float* __restrict__ adst)
{
    extern __shared__ float sm[];
    float* sWhh = sm + E_WHH;
    float* sBhh = sm + E_BHH;
    float* sWc  = sm + E_WC;
    float* sBc  = sm + E_BC;
    float* sWxl = sm + E_WXL;
    float* sBxl = sm + E_BXL;
    float* sAs  = sm + E_AS;
    float* sAd  = sm + E_AD;
    u64*   hsu  = reinterpret_cast<u64*>(sm + E_HS);

    const int tid = threadIdx.x;
    for (int i = tid; i < 12288; i += 256) sWhh[i] = Whh[i];
    for (int i = tid; i < 2304;  i += 256) {
        int j = i / 12, c = i % 12;
        sWc[i] = (c < 10) ? g_Wc_enc[j * 10 + c] : 0.f;
    }
    if (tid < 192) { sBhh[tid] = bhh[tid]; sBc[tid] = g_bc_enc[tid]; }
    for (int i = tid; i < 640;   i += 256) sWxl[i] = g_Wc_xl[i];
    if (tid < 64) { sBxl[tid] = g_b_xl[tid]; sAs[tid] = asrc[tid]; sAd[tid] = adst[tid]; }
    __syncthreads();

    for (int tile = blockIdx.x; tile < TILES; tile += GRID) {

    const int bnA = tile * 512 + tid;
    const int bnB = bnA + 256;
    const float* xpA = x + ((size_t)(bnA / Nq) * (Tq * Nq) + (bnA % Nq)) * Fq;
    const float* xpB = x + ((size_t)(bnB / Nq) * (Tq * Nq) + (bnB % Nq)) * Fq;

    u64 h2a[32], h2b[32];
    #pragma unroll
    for (int k = 0; k < 32; k++) {
        h2a[k] = 0ULL; h2b[k] = 0ULL;
        hsu[k * 512 + tid] = 0ULL; hsu[k * 512 + tid + 256] = 0ULL;
    }

    u64 xqA[5], xqB[5];

    for (int t = 0; t < Tq; t++) {
        {
            const float2* a2 = reinterpret_cast<const float2*>(xpA + (size_t)t * (Nq * Fq));
            const float2* b2 = reinterpret_cast<const float2*>(xpB + (size_t)t * (Nq * Fq));
            #pragma unroll
            for (int c2 = 0; c2 < 5; c2++) {
                float2 va = a2[c2]; xqA[c2] = pk(va.x, va.y);
                float2 vb = b2[c2]; xqB[c2] = pk(vb.x, vb.y);
            }
        }

        #pragma unroll 1
        for (int jj = 0; jj < 32; jj++) {
            const int j = 2 * jj;
            const ulonglong2* wh0 = (const ulonglong2*)(sWhh + j * 64);
            const ulonglong2* wh1 = (const ulonglong2*)(sWhh + (j + 1) * 64);
            const ulonglong2* wh2 = (const ulonglong2*)(sWhh + (j + 64) * 64);
            const ulonglong2* wh3 = (const ulonglong2*)(sWhh + (j + 65) * 64);
            const ulonglong2* wh4 = (const ulonglong2*)(sWhh + (j + 128) * 64);
            const ulonglong2* wh5 = (const ulonglong2*)(sWhh + (j + 129) * 64);
            u64 rA0 = 0, rA1 = 0, zA0 = 0, zA1 = 0, nA0 = 0, nA1 = 0;
            u64 rB0 = 0, rB1 = 0, zB0 = 0, zB1 = 0, nB0 = 0, nB1 = 0;
            #pragma unroll
            for (int k4 = 0; k4 < 16; k4++) {
                u64 haA = h2a[2 * k4], hbA = h2a[2 * k4 + 1];
                u64 haB = h2b[2 * k4], hbB = h2b[2 * k4 + 1];
                ulonglong2 w;
                w = wh0[k4];
                rA0 = fma2(w.x, haA, rA0); rA0 = fma2(w.y, hbA, rA0);
                rB0 = fma2(w.x, haB, rB0); rB0 = fma2(w.y, hbB, rB0);
                w = wh1[k4];
                rA1 = fma2(w.x, haA, rA1); rA1 = fma2(w.y, hbA, rA1);
                rB1 = fma2(w.x, haB, rB1); rB1 = fma2(w.y, hbB, rB1);
                w = wh2[k4];
                zA0 = fma2(w.x, haA, zA0); zA0 = fma2(w.y, hbA, zA0);
                zB0 = fma2(w.x, haB, zB0); zB0 = fma2(w.y, hbB, zB0);
                w = wh3[k4];
                zA1 = fma2(w.x, haA, zA1); zA1 = fma2(w.y, hbA, zA1);
                zB1 = fma2(w.x, haB, zB1); zB1 = fma2(w.y, hbB, zB1);
                w = wh4[k4];
                nA0 = fma2(w.x, haA, nA0); nA0 = fma2(w.y, hbA, nA0);
                nB0 = fma2(w.x, haB, nB0); nB0 = fma2(w.y, hbB, nB0);
                w = wh5[k4];
                nA1 = fma2(w.x, haA, nA1); nA1 = fma2(w.y, hbA, nA1);
                nB1 = fma2(w.x, haB, nB1); nB1 = fma2(w.y, hbB, nB1);
            }
            const u64* cx0 = (const u64*)(sWc + j * 12);
            const u64* cx1 = (const u64*)(sWc + (j + 1) * 12);
            const u64* cx2 = (const u64*)(sWc + (j + 64) * 12);
            const u64* cx3 = (const u64*)(sWc + (j + 65) * 12);
            const u64* cx4 = (const u64*)(sWc + (j + 128) * 12);
            const u64* cx5 = (const u64*)(sWc + (j + 129) * 12);
            u64 xnA0 = 0, xnA1 = 0, xnB0 = 0, xnB1 = 0;
            #pragma unroll
            for (int c2 = 0; c2 < 5; c2++) {
                u64 xa = xqA[c2], xb = xqB[c2];
                u64 c0 = cx0[c2], c1 = cx1[c2], c2v = cx2[c2],
                    c3 = cx3[c2], c4 = cx4[c2], c5 = cx5[c2];
                rA0  = fma2(c0, xa, rA0);   rB0  = fma2(c0, xb, rB0);
                rA1  = fma2(c1, xa, rA1);   rB1  = fma2(c1, xb, rB1);
                zA0  = fma2(c2v, xa, zA0);  zB0  = fma2(c2v, xb, zB0);
                zA1  = fma2(c3, xa, zA1);   zB1  = fma2(c3, xb, zB1);
                xnA0 = fma2(c4, xa, xnA0);  xnB0 = fma2(c4, xb, xnB0);
                xnA1 = fma2(c5, xa, xnA1);  xnB1 = fma2(c5, xb, xnB1);
            }
            float b0 = sBhh[j] + sBc[j], b1 = sBhh[j + 1] + sBc[j + 1];
            float b2 = sBhh[j + 64] + sBc[j + 64], b3 = sBhh[j + 65] + sBc[j + 65];
            float bn0 = sBhh[j + 128], bn1 = sBhh[j + 129];
            float bx0 = sBc[j + 128],  bx1 = sBc[j + 129];
            {
                float R0 = sigmf(hadd(rA0) + b0);
                float R1 = sigmf(hadd(rA1) + b1);
                float Z0 = sigmf(hadd(zA0) + b2);
                float Z1 = sigmf(hadd(zA1) + b3);
                float N0 = tanhf_(hadd(xnA0) + bx0 + R0 * (hadd(nA0) + bn0));
                float N1 = tanhf_(hadd(xnA1) + bx1 + R1 * (hadd(nA1) + bn1));
                float2 ho = unpk(hsu[jj * 512 + tid]);
                hsu[jj * 512 + tid] = pk((1.f - Z0) * N0 + Z0 * ho.x,
                                         (1.f - Z1) * N1 + Z1 * ho.y);
            }
            {
                float R0 = sigmf(hadd(rB0) + b0);
                float R1 = sigmf(hadd(rB1) + b1);
                float Z0 = sigmf(hadd(zB0) + b2);
                float Z1 = sigmf(hadd(zB1) + b3);
                float N0 = tanhf_(hadd(xnB0) + bx0 + R0 * (hadd(nB0) + bn0));
                float N1 = tanhf_(hadd(xnB1) + bx1 + R1 * (hadd(nB1) + bn1));
                float2 ho = unpk(hsu[jj * 512 + tid + 256]);
                hsu[jj * 512 + tid + 256] = pk((1.f - Z0) * N0 + Z0 * ho.x,
                                               (1.f - Z1) * N1 + Z1 * ho.y);
            }
        }
        #pragma unroll
        for (int k = 0; k < 32; k++) {
            h2a[k] = hsu[k * 512 + tid];
            h2b[k] = hsu[k * 512 + tid + 256];
        }
    }

    enc_epi(bnA, xqA, h2a, sWxl, sBxl, sAs, sAd);
    enc_epi(bnB, xqB, h2b, sWxl, sBxl, sAs, sAd);

    }   // tile loop
}

// ------------------------- GAT + conf ---------------------------------------
__global__ void __launch_bounds__(128) gat_kernel(
    const float* __restrict__ gat_b,
    const float* __restrict__ cW1,
    const float* __restrict__ cB1,
    const float* __restrict__ cW2,
    const float* __restrict__ cB2,
    float* __restrict__ out)
{
    __shared__ __align__(16) float sW1t[4096];   // [m][k]
    __shared__ __align__(16) float sB1[64];
    __shared__ __align__(16) float sW2[512];     // [m][p] padded stride 8
    __shared__ __align__(16) float sB2[8];
    __shared__ __align__(16) float sGb[64];

    const int tid = threadIdx.x;
    for (int i = tid; i < 4096; i += 128) {
        int m = i >> 6, k = i & 63;
        sW1t[i] = cW1[k * 64 + m];
    }
    for (int i = tid; i < 512; i += 128) {
        int m = i >> 3, p = i & 7;
        sW2[i] = (p < 5) ? cW2[m * 5 + p] : 0.f;
    }
    if (tid < 64) { sB1[tid] = cB1[tid]; sGb[tid] = gat_b[tid]; }
    if (tid < 8)  sB2[tid] = (tid < 5) ? cB2[tid] : 0.f;
    __syncthreads();

    const int bn = blockIdx.x * 128 + tid;
    const int b  = bn / Nq;
    const int n  = bn % Nq;
    const int base = b * Nq;

    float ad_i = g_ad[bn];
    int   mi   = g_mask[bn];

    float w[5];
    float amax = -1e30f;
    #pragma unroll
    for (int j = 0; j < 5; j++) {
        int src = base + j;
        float a = g_as[src] + ad_i;
        a = a > 0.f ? a : 0.2f * a;
        bool valid = (j == n) ? true : (mi && g_mask[src]);
        w[j] = valid ? a : -1e30f;
        amax = fmaxf(amax, w[j]);
    }
    float denom = 0.f;
    #pragma unroll
    for (int j = 0; j < 5; j++) {
        float e = __expf(w[j] - amax);
        w[j] = e;
        denom += e;
    }
    float inv = __fdividef(1.f, denom);
    #pragma unroll
    for (int j = 0; j < 5; j++) w[j] *= inv;

    u64 acc2[32];
    #pragma unroll
    for (int k = 0; k < 32; k++) acc2[k] = 0ULL;
    #pragma unroll
    for (int j = 0; j < 5; j++) {
        const u64* xr = reinterpret_cast<const u64*>(g_xl) + (size_t)(base + j) * 32;
        u64 wj = bc2(w[j]);
        #pragma unroll
        for (int k = 0; k < 32; k++) acc2[k] = fma2(wj, xr[k], acc2[k]);
    }

    u64 hfp[32];
    const u64* he = reinterpret_cast<const u64*>(g_henc) + (size_t)bn * 32;
    const u64* gb = (const u64*)sGb;
    u64* hfo = reinterpret_cast<u64*>(g_hfin) + (size_t)bn * 32;
    #pragma unroll
    for (int k = 0; k < 32; k++) {
        u64 r = add2(add2(he[k], acc2[k]), gb[k]);
        hfp[k] = r;
        hfo[k] = r;
    }

    u64 o2p[3];
    o2p[0] = pk(sB2[0], sB2[1]);
    o2p[1] = pk(sB2[2], sB2[3]);
    o2p[2] = pk(sB2[4], 0.f);
    #pragma unroll 2
    for (int m = 0; m < 64; m++) {
        const ulonglong2* w1 = (const ulonglong2*)(sW1t + m * 64);
        u64 acc = 0;
        #pragma unroll
        for (int k4 = 0; k4 < 16; k4++) {
            ulonglong2 wv = w1[k4];
            acc = fma2(wv.x, hfp[2 * k4], acc);
            acc = fma2(wv.y, hfp[2 * k4 + 1], acc);
        }
        float t = fmaxf(hadd(acc) + sB1[m], 0.f);
        u64 t2 = bc2(t);
        const u64* w2r = (const u64*)(sW2 + m * 8);
        o2p[0] = fma2(t2, w2r[0], o2p[0]);
        o2p[1] = fma2(t2, w2r[1], o2p[1]);
        o2p[2] = fma2(t2, w2r[2], o2p[2]);
    }
    float o[5];
    { float2 a = unpk(o2p[0]); o[0] = a.x; o[1] = a.y; }
    { float2 a = unpk(o2p[1]); o[2] = a.x; o[3] = a.y; }
    { float2 a = unpk(o2p[2]); o[4] = a.x; }
    float mx = o[0];
    #pragma unroll
    for (int p = 1; p < 5; p++) mx = fmaxf(mx, o[p]);
    float s = 0.f;
    #pragma unroll
    for (int p = 0; p < 5; p++) { o[p] = __expf(o[p] - mx); s += o[p]; }
    float invs = __fdividef(1.f, s);

    float* conf = out + TRAJ_ELEMS;
    #pragma unroll
    for (int p = 0; p < 5; p++)
        conf[(size_t)b * 25 + p * 5 + n] = o[p] * invs;
}

// ------------------------- decoder ------------------------------------------
// 256 threads, 2 nodes/thread, persistent over tiles of 512 nodes.
// smem floats:
//  sWhh 12288 | sBhh 192 | sWcd 384 | sBcd 192 | sW1t 4096 | sB1 64 |
//  sW2p 768 (stride 12) | sB2 16 | hs 32*512 u64
constexpr int D_WHH = 0;
constexpr int D_BHH = 12288;
constexpr int D_WCD = 12480;
constexpr int D_BCD = 12864;
constexpr int D_W1T = 13056;
constexpr int D_B1  = 17152;
constexpr int D_W2  = 17216;
constexpr int D_B2  = 17984;
constexpr int D_HS  = 18000;
constexpr int DEC_SMEM_FLOATS = D_HS + 32 * 512 * 2;   // 50768
constexpr int DEC_SMEM_BYTES  = DEC_SMEM_FLOATS * 4;   // 203072

__global__ void __launch_bounds__(256) dec_kernel(
    const float* __restrict__ x,
    const float* __restrict__ Whh,
    const float* __restrict__ bhh,
    const float* __restrict__ oW1,
    const float* __restrict__ oB1,
    const float* __restrict__ oW2,
    const float* __restrict__ oB2,
    float* __restrict__ out)
{
    extern __shared__ float sm[];
    float* sWhh = sm + D_WHH;
    float* sBhh = sm + D_BHH;
    float* sWcd = sm + D_WCD;
    float* sBcd = sm + D_BCD;
    float* sW1t = sm + D_W1T;
    float* sB1  = sm + D_B1;
    float* sW2p = sm + D_W2;
    float* sB2  = sm + D_B2;
    u64*   hsu  = reinterpret_cast<u64*>(sm + D_HS);

    const int tid = threadIdx.x;
    for (int i = tid; i < 12288; i += 256) sWhh[i] = Whh[i];
    if (tid < 192) { sBhh[tid] = bhh[tid]; sBcd[tid] = g_bc_dec[tid]; }
    for (int i = tid; i < 384;   i += 256) sWcd[i] = g_Wc_dec[i];
    for (int i = tid; i < 4096;  i += 256) {
        int m = i >> 6, k = i & 63;
        sW1t[i] = oW1[k * 64 + m];
    }
    for (int i = tid; i < 768;   i += 256) {
        int m = i / 12, c = i % 12;
        sW2p[i] = (c < 10) ? oW2[m * 10 + c] : 0.f;
    }
    if (tid < 64) sB1[tid] = oB1[tid];
    if (tid < 16) sB2[tid] = (tid < 10) ? oB2[tid] : 0.f;
    __syncthreads();

    for (int tile = blockIdx.x; tile < TILES; tile += GRID) {

    const int bnA = tile * 512 + tid;
    const int bnB = bnA + 256;
    const int bA = bnA / Nq, nA = bnA % Nq;
    const int bB = bnB / Nq, nB = bnB % Nq;

    u64 h2a[32], h2b[32];
    {
        const u64* hfA = reinterpret_cast<const u64*>(g_hfin) + (size_t)bnA * 32;
        const u64* hfB = reinterpret_cast<const u64*>(g_hfin) + (size_t)bnB * 32;
        #pragma unroll
        for (int k = 0; k < 32; k++) {
            h2a[k] = hfA[k]; hsu[k * 512 + tid] = h2a[k];
            h2b[k] = hfB[k]; hsu[k * 512 + tid + 256] = h2b[k];
        }
    }

    const float* xlA = x + ((size_t)bA * (Tq * Nq) + 4 * Nq + nA) * Fq;
    const float* xlB = x + ((size_t)bB * (Tq * Nq) + 4 * Nq + nB) * Fq;
    float xyA0 = xlA[0], xyA1 = xlA[1];
    float xyB0 = xlB[0], xyB1 = xlB[1];

    for (int t = 0; t < TOq; t++) {
        #pragma unroll 1
        for (int jj = 0; jj < 32; jj++) {
            const int j = 2 * jj;
            const ulonglong2* wh0 = (const ulonglong2*)(sWhh + j * 64);
            const ulonglong2* wh1 = (const ulonglong2*)(sWhh + (j + 1) * 64);
            const ulonglong2* wh2 = (const ulonglong2*)(sWhh + (j + 64) * 64);
            const ulonglong2* wh3 = (const ulonglong2*)(sWhh + (j + 65) * 64);
            const ulonglong2* wh4 = (const ulonglong2*)(sWhh + (j + 128) * 64);
            const ulonglong2* wh5 = (const ulonglong2*)(sWhh + (j + 129) * 64);
            u64 rA0 = 0, rA1 = 0, zA0 = 0, zA1 = 0, nA0 = 0, nA1 = 0;
            u64 rB0 = 0, rB1 = 0, zB0 = 0, zB1 = 0, nB0 = 0, nB1 = 0;
            #pragma unroll
            for (int k4 = 0; k4 < 16; k4++) {
                u64 haA = h2a[2 * k4], hbA = h2a[2 * k4 + 1];
                u64 haB = h2b[2 * k4], hbB = h2b[2 * k4 + 1];
                ulonglong2 w;
                w = wh0[k4];
                rA0 = fma2(w.x, haA, rA0); rA0 = fma2(w.y, hbA, rA0);
                rB0 = fma2(w.x, haB, rB0); rB0 = fma2(w.y, hbB, rB0);
                w = wh1[k4];
                rA1 = fma2(w.x, haA, rA1); rA1 = fma2(w.y, hbA, rA1);
                rB1 = fma2(w.x, haB, rB1); rB1 = fma2(w.y, hbB, rB1);
                w = wh2[k4];
                zA0 = fma2(w.x, haA, zA0); zA0 = fma2(w.y, hbA, zA0);
                zB0 = fma2(w.x, haB, zB0); zB0 = fma2(w.y, hbB, zB0);
                w = wh3[k4];
                zA1 = fma2(w.x, haA, zA1); zA1 = fma2(w.y, hbA, zA1);
                zB1 = fma2(w.x, haB, zB1); zB1 = fma2(w.y, hbB, zB1);
                w = wh4[k4];
                nA0 = fma2(w.x, haA, nA0); nA0 = fma2(w.y, hbA, nA0);
                nB0 = fma2(w.x, haB, nB0); nB0 = fma2(w.y, hbB, nB0);
                w = wh5[k4];
                nA1 = fma2(w.x, haA, nA1); nA1 = fma2(w.y, hbA, nA1);
                nB1 = fma2(w.x, haB, nB1); nB1 = fma2(w.y, hbB, nB1);
            }
            float w00 = sWcd[j * 2],         w01 = sWcd[j * 2 + 1];
            float w10 = sWcd[(j + 1) * 2],   w11 = sWcd[(j + 1) * 2 + 1];
            float w20 = sWcd[(j + 64) * 2],  w21 = sWcd[(j + 64) * 2 + 1];
            float w30 = sWcd[(j + 65) * 2],  w31 = sWcd[(j + 65) * 2 + 1];
            float w40 = sWcd[(j + 128) * 2], w41 = sWcd[(j + 128) * 2 + 1];
            float w50 = sWcd[(j + 129) * 2], w51 = sWcd[(j + 129) * 2 + 1];
            float br0 = sBcd[j] + sBhh[j],           br1 = sBcd[j + 1] + sBhh[j + 1];
            float bz0 = sBcd[j + 64] + sBhh[j + 64], bz1 = sBcd[j + 65] + sBhh[j + 65];
            float bxn0 = sBcd[j + 128], bxn1 = sBcd[j + 129];
            float bn0 = sBhh[j + 128],  bn1 = sBhh[j + 129];
            {
                float R0 = sigmf(hadd(rA0) + br0 + w00 * xyA0 + w01 * xyA1);
                float R1 = sigmf(hadd(rA1) + br1 + w10 * xyA0 + w11 * xyA1);
                float Z0 = sigmf(hadd(zA0) + bz0 + w20 * xyA0 + w21 * xyA1);
                float Z1 = sigmf(hadd(zA1) + bz1 + w30 * xyA0 + w31 * xyA1);
                float N0 = tanhf_(bxn0 + w40 * xyA0 + w41 * xyA1 + R0 * (hadd(nA0) + bn0));
                float N1 = tanhf_(bxn1 + w50 * xyA0 + w51 * xyA1 + R1 * (hadd(nA1) + bn1));
                float2 ho = unpk(hsu[jj * 512 + tid]);
                hsu[jj * 512 + tid] = pk((1.f - Z0) * N0 + Z0 * ho.x,
                                         (1.f - Z1) * N1 + Z1 * ho.y);
            }
            {
                float R0 = sigmf(hadd(rB0) + br0 + w00 * xyB0 + w01 * xyB1);
                float R1 = sigmf(hadd(rB1) + br1 + w10 * xyB0 + w11 * xyB1);
                float Z0 = sigmf(hadd(zB0) + bz0 + w20 * xyB0 + w21 * xyB1);
                float Z1 = sigmf(hadd(zB1) + bz1 + w30 * xyB0 + w31 * xyB1);
                float N0 = tanhf_(bxn0 + w40 * xyB0 + w41 * xyB1 + R0 * (hadd(nB0) + bn0));
                float N1 = tanhf_(bxn1 + w50 * xyB0 + w51 * xyB1 + R1 * (hadd(nB1) + bn1));
                float2 ho = unpk(hsu[jj * 512 + tid + 256]);
                hsu[jj * 512 + tid + 256] = pk((1.f - Z0) * N0 + Z0 * ho.x,
                                               (1.f - Z1) * N1 + Z1 * ho.y);
            }
        }
        #pragma unroll
        for (int k = 0; k < 32; k++) {
            h2a[k] = hsu[k * 512 + tid];
            h2b[k] = hsu[k * 512 + tid + 256];
        }

        // out MLP for both nodes, shared weight loads
        u64 oA[5], oB[5];
        #pragma unroll
        for (int p = 0; p < 5; p++) {
            oA[p] = pk(sB2[2 * p], sB2[2 * p + 1]);
            oB[p] = oA[p];
        }
        #pragma unroll 2
        for (int m = 0; m < 64; m++) {
            const ulonglong2* w1 = (const ulonglong2*)(sW1t + m * 64);
            u64 accA = 0, accB = 0;
            #pragma unroll
            for (int k4 = 0; k4 < 16; k4++) {
                ulonglong2 wv = w1[k4];
                accA = fma2(wv.x, h2a[2 * k4], accA);
                accA = fma2(wv.y, h2a[2 * k4 + 1], accA);
                accB = fma2(wv.x, h2b[2 * k4], accB);
                accB = fma2(wv.y, h2b[2 * k4 + 1], accB);
            }
            float aA = fmaxf(hadd(accA) + sB1[m], 0.f);
            float aB = fmaxf(hadd(accB) + sB1[m], 0.f);
            u64 aA2 = bc2(aA), aB2 = bc2(aB);
            const u64* w2r = (const u64*)(sW2p + m * 12);
            #pragma unroll
            for (int p = 0; p < 5; p++) {
                u64 wv = w2r[p];
                oA[p] = fma2(aA2, wv, oA[p]);
                oB[p] = fma2(aB2, wv, oB[p]);
            }
        }

        float foA[10], foB[10];
        #pragma unroll
        for (int p = 0; p < 5; p++) {
            float2 va = unpk(oA[p]); foA[2 * p] = va.x; foA[2 * p + 1] = va.y;
            float2 vb = unpk(oB[p]); foB[2 * p] = vb.x; foB[2 * p + 1] = vb.y;
        }

        size_t obA = (size_t)bA * 300 + (size_t)nA * 12 + t * 2;
        size_t obB = (size_t)bB * 300 + (size_t)nB * 12 + t * 2;
        #pragma unroll
        for (int m = 0; m < 5; m++) {
            out[obA + m * 60 + 0] = foA[m];
            out[obA + m * 60 + 1] = foA[5 + m];
            out[obB + m * 60 + 0] = foB[m];
            out[obB + m * 60 + 1] = foB[5 + m];
        }
        xyA0 = foA[0]; xyA1 = foA[5];
        xyB0 = foB[0]; xyB1 = foB[5];
    }

    }   // tile loop
}

// ------------------------- launch -------------------------------------------
extern "C" void kernel_launch(void* const* d_in, const int* in_sizes, int n_in,
                              void* d_out, int out_size)
{
    const float* x        = (const float*)d_in[0];
    const float* embW     = (const float*)d_in[1];
    const float* embB     = (const float*)d_in[2];
    const float* gatW     = (const float*)d_in[3];
    const float* attSrc   = (const float*)d_in[4];
    const float* attDst   = (const float*)d_in[5];
    const float* gatB     = (const float*)d_in[6];
    const float* encWih   = (const float*)d_in[7];
    const float* encWhh   = (const float*)d_in[8];
    const float* encBih   = (const float*)d_in[9];
    const float* encBhh   = (const float*)d_in[10];
    const float* decWih   = (const float*)d_in[11];
    const float* decWhh   = (const float*)d_in[12];
    const float* decBih   = (const float*)d_in[13];
    const float* decBhh   = (const float*)d_in[14];
    const float* oW1      = (const float*)d_in[15];
    const float* oB1      = (const float*)d_in[16];
    const float* oW2      = (const float*)d_in[17];
    const float* oB2      = (const float*)d_in[18];
    const float* projW    = (const float*)d_in[19];
    const float* projB    = (const float*)d_in[20];
    const float* cW1      = (const float*)d_in[21];
    const float* cB1      = (const float*)d_in[22];
    const float* cW2      = (const float*)d_in[23];
    const float* cB2      = (const float*)d_in[24];
    float* out = (float*)d_out;

    cudaFuncSetAttribute(enc_kernel, cudaFuncAttributeMaxDynamicSharedMemorySize, ENC_SMEM_BYTES);
    cudaFuncSetAttribute(dec_kernel, cudaFuncAttributeMaxDynamicSharedMemorySize, DEC_SMEM_BYTES);

    prep_kernel<<<27, 128>>>(encWih, encBih, decWih, decBih,
                             embW, embB, projW, projB, gatW);

    enc_kernel<<<GRID, 256, ENC_SMEM_BYTES>>>(x, encWhh, encBhh, attSrc, attDst);

    gat_kernel<<<BNq / 128, 128>>>(gatB, cW1, cB1, cW2, cB2, out);

    dec_kernel<<<GRID, 256, DEC_SMEM_BYTES>>>(x, decWhh, decBhh,
                                              oW1, oB1, oW2, oB2, out);
}